// round 6
// baseline (speedup 1.0000x reference)
#include <cuda_runtime.h>
#include <cuda_bf16.h>
#include <cstdint>

#define HW 16384
#define IMG 128

// ---------------- scratch (static __device__, no allocs) ----------------
__device__ float g_t[8L * 384 * HW];            // pos-conv output (B,384,H,W) fp32
__device__ float g_q[8L * 128 * HW];            // q channels fp32
__device__ float g_k[8L * 128 * HW];            // k channels fp32
__device__ __nv_bfloat16 g_xh[8L * 128 * HW];   // x split hi
__device__ __nv_bfloat16 g_xl[8L * 128 * HW];   // x split lo
__device__ __nv_bfloat16 g_yh[8L * 256 * HW];   // [v|d3|d5] split hi
__device__ __nv_bfloat16 g_yl[8L * 256 * HW];   // [v|d3|d5] split lo
__device__ __nv_bfloat16 g_wh[384 * 128];       // pos_w split hi
__device__ __nv_bfloat16 g_wl[384 * 128];       // pos_w split lo
__device__ __nv_bfloat16 g_Ah[8 * 128 * 256];   // folded proj*attn split hi
__device__ __nv_bfloat16 g_Al[8 * 128 * 256];   // folded proj*attn split lo
__device__ float g_gram[64 * 288];              // per (b,h): G[256], qn[16], kn[16]

__device__ __forceinline__ void split2(float v, __nv_bfloat16& h, __nv_bfloat16& l) {
    h = __float2bfloat16(v);
    l = __float2bfloat16(v - __bfloat162float(h));
}

// ---------------- zero gram accumulators ----------------
__global__ void zero_gram_k() {
    int i = blockIdx.x * 256 + threadIdx.x;
    if (i < 64 * 288) g_gram[i] = 0.f;
}

// ---------------- split conversions ----------------
__global__ void convert_x_k(const float* __restrict__ x) {
    long i = ((long)blockIdx.x * 256 + threadIdx.x) * 4;
    float4 v = *(const float4*)(x + i);
    __nv_bfloat16 h, l;
    split2(v.x, h, l); g_xh[i + 0] = h; g_xl[i + 0] = l;
    split2(v.y, h, l); g_xh[i + 1] = h; g_xl[i + 1] = l;
    split2(v.z, h, l); g_xh[i + 2] = h; g_xl[i + 2] = l;
    split2(v.w, h, l); g_xh[i + 3] = h; g_xl[i + 3] = l;
}
__global__ void convert_w_k(const float* __restrict__ w) {
    long i = ((long)blockIdx.x * 256 + threadIdx.x) * 4;
    float4 v = *(const float4*)(w + i);
    __nv_bfloat16 h, l;
    split2(v.x, h, l); g_wh[i + 0] = h; g_wl[i + 0] = l;
    split2(v.y, h, l); g_wh[i + 1] = h; g_wl[i + 1] = l;
    split2(v.z, h, l); g_wh[i + 2] = h; g_wl[i + 2] = l;
    split2(v.w, h, l); g_wh[i + 3] = h; g_wl[i + 3] = l;
}

// ---------------- mma.sync bf16-split GEMM ----------------
// C[b](M x 16384) = (Ah+Al)(M x K) @ (Bh+Bl)(K x 16384) via 3 terms:
//   term0: Ah@Bh, term1: Al@Bh, term2: Ah@Bl  (fp32 accum, Al@Bl dropped ~2^-32)
// CTA tile 128M x 64N, 8 warps (4x2), warp tile 32x32, m16n8k16.
__device__ __forceinline__ void hmma(float* c, const uint32_t* a, uint32_t b0, uint32_t b1) {
    asm volatile(
        "mma.sync.aligned.m16n8k16.row.col.f32.bf16.bf16.f32 "
        "{%0,%1,%2,%3}, {%4,%5,%6,%7}, {%8,%9}, {%0,%1,%2,%3};"
        : "+f"(c[0]), "+f"(c[1]), "+f"(c[2]), "+f"(c[3])
        : "r"(a[0]), "r"(a[1]), "r"(a[2]), "r"(a[3]), "r"(b0), "r"(b1));
}

template <int K>
__device__ __forceinline__ void mmasync_body(
    const __nv_bfloat16* __restrict__ Ah, const __nv_bfloat16* __restrict__ Al,
    long aStride,
    const __nv_bfloat16* __restrict__ Bh, const __nv_bfloat16* __restrict__ Bl,
    long bStride,
    float* __restrict__ C, long cStride, const float* __restrict__ bias)
{
    __shared__ __nv_bfloat16 As[128][36];
    __shared__ __nv_bfloat16 Bs[64][36];

    const int b = blockIdx.z;
    const int m0 = blockIdx.y * 128;
    const int n0 = blockIdx.x * 64;
    const int tid = threadIdx.x;
    const int wid = tid >> 5, lane = tid & 31;
    const int wm = (wid & 3) * 32, wn = (wid >> 2) * 32;
    const int g = lane >> 2, tq = lane & 3;

    float c[2][4][4];
#pragma unroll
    for (int mi = 0; mi < 2; mi++)
#pragma unroll
        for (int ni = 0; ni < 4; ni++)
#pragma unroll
            for (int j = 0; j < 4; j++) c[mi][ni][j] = 0.f;

    const int KC = K / 32;        // physical k32 chunks per term
    const int NC = 3 * KC;        // virtual chunks

    // fill indices (constant across chunks)
    const int fam = tid >> 2, fak = (tid & 3) * 8;            // A: rows, col-octet (2 passes)
    const int fbk = tid >> 3, fbn = (tid & 7) * 8;            // B: one k-row, 8 n

    for (int cc = 0; cc < NC; cc++) {
        const int t = cc / KC;
        const int ko = (cc - t * KC) * 32;
        const __nv_bfloat16* Asrc = ((t == 1) ? Al : Ah) + (long)b * aStride;
        const __nv_bfloat16* Bsrc = ((t == 2) ? Bl : Bh) + (long)b * bStride;

        // A tile 128x32 (K-contiguous, coalesced)
#pragma unroll
        for (int pass = 0; pass < 2; pass++) {
            int m = fam + pass * 64;
            uint4 v = *(const uint4*)(Asrc + (long)(m0 + m) * K + ko + fak);
            *(uint2*)&As[m][fak] = make_uint2(v.x, v.y);
            *(uint2*)&As[m][fak + 4] = make_uint2(v.z, v.w);
        }
        // B tile 32x64 -> transposed into Bs[n][k]
        {
            uint4 v = *(const uint4*)(Bsrc + (long)(ko + fbk) * HW + n0 + fbn);
            __nv_bfloat16 tmp[8];
            *(uint4*)tmp = v;
#pragma unroll
            for (int j = 0; j < 8; j++) Bs[fbn + j][fbk] = tmp[j];
        }
        __syncthreads();

#pragma unroll
        for (int kc = 0; kc < 2; kc++) {
            uint32_t a[2][4];
#pragma unroll
            for (int mi = 0; mi < 2; mi++) {
                int rb = wm + mi * 16;
                a[mi][0] = *(const uint32_t*)&As[rb + g][kc * 16 + tq * 2];
                a[mi][1] = *(const uint32_t*)&As[rb + g + 8][kc * 16 + tq * 2];
                a[mi][2] = *(const uint32_t*)&As[rb + g][kc * 16 + tq * 2 + 8];
                a[mi][3] = *(const uint32_t*)&As[rb + g + 8][kc * 16 + tq * 2 + 8];
            }
#pragma unroll
            for (int ni = 0; ni < 4; ni++) {
                uint32_t b0 = *(const uint32_t*)&Bs[wn + ni * 8 + g][kc * 16 + tq * 2];
                uint32_t b1 = *(const uint32_t*)&Bs[wn + ni * 8 + g][kc * 16 + tq * 2 + 8];
#pragma unroll
                for (int mi = 0; mi < 2; mi++) hmma(c[mi][ni], a[mi], b0, b1);
            }
        }
        __syncthreads();
    }

    // epilogue: fragment rows g / g+8, cols tq*2, tq*2+1
#pragma unroll
    for (int mi = 0; mi < 2; mi++) {
        int r0 = m0 + wm + mi * 16 + g;
        float bv0 = bias ? bias[r0] : 0.f;
        float bv1 = bias ? bias[r0 + 8] : 0.f;
#pragma unroll
        for (int ni = 0; ni < 4; ni++) {
            int col = n0 + wn + ni * 8 + tq * 2;
            float* p0 = C + (long)b * cStride + (long)r0 * HW + col;
            float* p1 = p0 + 8L * HW;
            *(float2*)p0 = make_float2(c[mi][ni][0] + bv0, c[mi][ni][1] + bv0);
            *(float2*)p1 = make_float2(c[mi][ni][2] + bv1, c[mi][ni][3] + bv1);
        }
    }
}

__global__ __launch_bounds__(256) void k1_gemm(const float* __restrict__ pb) {
    mmasync_body<128>(g_wh, g_wl, 0L, g_xh, g_xl, 128L * HW, g_t, 384L * HW, pb);
}
__global__ __launch_bounds__(256) void k4_gemm(float* __restrict__ out) {
    mmasync_body<256>(g_Ah, g_Al, 128L * 256, g_yh, g_yl, 256L * HW, out, 128L * HW, nullptr);
}

// ---------------- dual grouped conv (3x3 + 5x5 sharing input pair) ----------------
// MODE 0: in = g_t (192 groups) -> q/k fp32, v -> y bf16-split.
// MODE 1: in = x (64 groups) -> y[128..191] (3x3), y[192..255] (5x5), bf16-split.
template <int MODE>
__global__ __launch_bounds__(256, 3) void dualconv_k(
    const float* __restrict__ in_ext,
    const float* __restrict__ w3, const float* __restrict__ b3,
    const float* __restrict__ w5, const float* __restrict__ b5)
{
    const int Cin = (MODE == 0) ? 384 : 128;
    const float* in = (MODE == 0) ? (const float*)g_t : in_ext;

    __shared__ float s[2 * 68 * 68];
    __shared__ float sw[68];

    const int tile = blockIdx.x;
    const int oy0 = (tile >> 1) * 64;
    const int ox0 = (tile & 1) * 64;
    const int g = blockIdx.y;
    const long bz = blockIdx.z;
    const int tid = threadIdx.x;
    const int ttx = tid & 15, tty = tid >> 4;
    const int py0 = tty * 4, px0 = ttx * 4;

    const float* in0 = in + (bz * Cin + 2 * g) * (long)HW;
    for (int idx = tid; idx < 2 * 68 * 68; idx += 256) {
        int ch = idx / 4624;
        int rem = idx - ch * 4624;
        int r = rem / 68, cc = rem - r * 68;
        int gy = oy0 - 2 + r, gx = ox0 - 2 + cc;
        float v = 0.f;
        if ((unsigned)gy < 128u && (unsigned)gx < 128u)
            v = in0[ch * HW + gy * IMG + gx];
        s[idx] = v;
    }
    if (tid < 50) sw[tid] = w5[g * 50 + tid];
    else if (tid < 68) sw[tid] = w3[g * 18 + (tid - 50)];
    __syncthreads();

    const float bias3 = b3[g], bias5 = b5[g];
    // routing
    float* f3 = nullptr; long y3 = -1;
    float* f5 = nullptr; long y5 = -1;
    if (MODE == 0) {
        if (g < 128) f3 = &g_q[(bz * 128 + g) * HW];
        else         f3 = &g_k[(bz * 128 + (g - 128)) * HW];
        if (g < 64)  f5 = &g_k[(bz * 128 + 64 + g) * HW];
        else         y5 = (bz * 256 + (g - 64)) * HW;
    } else {
        y3 = (bz * 256 + 128 + g) * HW;
        y5 = (bz * 256 + 192 + g) * HW;
    }

#pragma unroll
    for (int half = 0; half < 2; half++) {
        float a3[2][4], a5[2][4];
#pragma unroll
        for (int i = 0; i < 2; i++)
#pragma unroll
            for (int j = 0; j < 4; j++) { a3[i][j] = 0.f; a5[i][j] = 0.f; }

#pragma unroll
        for (int ic = 0; ic < 2; ++ic) {
            const float* sc = s + ic * 4624 + (py0 + half * 2) * 68 + px0;
            float r[6][8];
#pragma unroll
            for (int dy = 0; dy < 6; dy++)
#pragma unroll
                for (int dx = 0; dx < 8; dx++) r[dy][dx] = sc[dy * 68 + dx];
            const float* w5s = sw + ic * 25;
#pragma unroll
            for (int t = 0; t < 25; t++) {
                float wv = w5s[t];
                int ky = t / 5, kx = t % 5;
#pragma unroll
                for (int oy = 0; oy < 2; oy++)
#pragma unroll
                    for (int ox = 0; ox < 4; ox++)
                        a5[oy][ox] += r[oy + ky][ox + kx] * wv;
            }
            const float* w3s = sw + 50 + ic * 9;
#pragma unroll
            for (int t = 0; t < 9; t++) {
                float wv = w3s[t];
                int ky = t / 3, kx = t % 3;
#pragma unroll
                for (int oy = 0; oy < 2; oy++)
#pragma unroll
                    for (int ox = 0; ox < 4; ox++)
                        a3[oy][ox] += r[oy + 1 + ky][ox + 1 + kx] * wv;
            }
        }

#pragma unroll
        for (int oy = 0; oy < 2; oy++) {
            int off = (oy0 + py0 + half * 2 + oy) * IMG + ox0 + px0;
#pragma unroll
            for (int ox = 0; ox < 4; ox++) {
                float v3 = a3[oy][ox] + bias3;
                float v5 = a5[oy][ox] + bias5;
                if (f3) f3[off + ox] = v3;
                else { __nv_bfloat16 h, l; split2(v3, h, l); g_yh[y3 + off + ox] = h; g_yl[y3 + off + ox] = l; }
                if (f5) f5[off + ox] = v5;
                else { __nv_bfloat16 h, l; split2(v5, h, l); g_yh[y5 + off + ox] = h; g_yl[y5 + off + ox] = l; }
            }
        }
    }
}

// ---------------- gram: per (b,h): G[16][16] = q @ k^T over pixels + sq norms ------
__global__ __launch_bounds__(256) void gram_k()
{
    const int bh = blockIdx.x;
    const int slice = blockIdx.y;
    const int b = bh >> 3, h = bh & 7;
    const float* qp = g_q + (long)(b * 128 + h * 16) * HW + slice * 1024;
    const float* kp = g_k + (long)(b * 128 + h * 16) * HW + slice * 1024;

    __shared__ float sq[64][17];
    __shared__ float sk[64][17];
    const int tid = threadIdx.x;
    const int phase = tid & 15, dg = (tid >> 4) & 3, eg = tid >> 6;

    float acc[4][4], aq[4], ak[4];
#pragma unroll
    for (int i = 0; i < 4; i++) {
        aq[i] = 0.f; ak[i] = 0.f;
#pragma unroll
        for (int j = 0; j < 4; j++) acc[i][j] = 0.f;
    }

    for (int blk = 0; blk < 16; ++blk) {
        for (int idx = tid; idx < 1024; idx += 256) {
            int d = idx >> 6, p = idx & 63;
            sq[p][d] = qp[(long)d * HW + blk * 64 + p];
            sk[p][d] = kp[(long)d * HW + blk * 64 + p];
        }
        __syncthreads();
        for (int p = phase; p < 64; p += 16) {
            float qv[4], kv[4];
#pragma unroll
            for (int i = 0; i < 4; i++) qv[i] = sq[p][dg * 4 + i];
#pragma unroll
            for (int j = 0; j < 4; j++) kv[j] = sk[p][eg * 4 + j];
#pragma unroll
            for (int i = 0; i < 4; i++)
#pragma unroll
                for (int j = 0; j < 4; j++) acc[i][j] += qv[i] * kv[j];
            if (eg == 0) {
#pragma unroll
                for (int i = 0; i < 4; i++) aq[i] += qv[i] * qv[i];
            }
            if (dg == 0) {
#pragma unroll
                for (int j = 0; j < 4; j++) ak[j] += kv[j] * kv[j];
            }
        }
        __syncthreads();
    }

    __shared__ float sG[288];
    for (int idx = tid; idx < 288; idx += 256) sG[idx] = 0.f;
    __syncthreads();
#pragma unroll
    for (int i = 0; i < 4; i++)
#pragma unroll
        for (int j = 0; j < 4; j++)
            atomicAdd(&sG[(dg * 4 + i) * 16 + eg * 4 + j], acc[i][j]);
    if (eg == 0) {
#pragma unroll
        for (int i = 0; i < 4; i++) atomicAdd(&sG[256 + dg * 4 + i], aq[i]);
    }
    if (dg == 0) {
#pragma unroll
        for (int j = 0; j < 4; j++) atomicAdd(&sG[272 + eg * 4 + j], ak[j]);
    }
    __syncthreads();
    float* gg = g_gram + bh * 288;
    for (int idx = tid; idx < 288; idx += 256) atomicAdd(gg + idx, sG[idx]);
}

// ---------------- attn: normalize gram, softmax, fold with proj into A (bf16 split) --
__global__ __launch_bounds__(256) void attn_k(
    const float* __restrict__ temp, const float* __restrict__ proj_w)
{
    const int b = blockIdx.x;
    const int part = blockIdx.y;
    const int tid = threadIdx.x;
    const long aBase = (long)b * 128 * 256;

    if (part == 8) {  // proj tail columns (same for all batches)
        for (int idx = tid; idx < 128 * 128; idx += 256) {
            int c = idx >> 7, j = idx & 127;
            __nv_bfloat16 h, l;
            split2(proj_w[c * 256 + 128 + j], h, l);
            g_Ah[aBase + c * 256 + 128 + j] = h;
            g_Al[aBase + c * 256 + 128 + j] = l;
        }
        return;
    }
    const int h = part;
    const float* gg = g_gram + (b * 8 + h) * 288;
    __shared__ float sA[256], sqn[16], skn[16], srm[16], srs[16];
    if (tid < 16) {
        sqn[tid] = fmaxf(sqrtf(gg[256 + tid]), 1e-12f);
        skn[tid] = fmaxf(sqrtf(gg[272 + tid]), 1e-12f);
    }
    __syncthreads();
    const int d = tid >> 4, e = tid & 15;
    float val = gg[d * 16 + e] / (sqn[d] * skn[e]) * temp[h];
    sA[tid] = val;
    __syncthreads();
    if (e == 0) {
        float m = -1e30f;
        for (int j = 0; j < 16; j++) m = fmaxf(m, sA[d * 16 + j]);
        srm[d] = m;
    }
    __syncthreads();
    float p = expf(val - srm[d]);
    sA[tid] = p;
    __syncthreads();
    if (e == 0) {
        float ssum = 0.f;
        for (int j = 0; j < 16; j++) ssum += sA[d * 16 + j];
        srs[d] = ssum;
    }
    __syncthreads();
    sA[tid] = p / srs[d];
    __syncthreads();
    for (int o = tid; o < 2048; o += 256) {
        int c = o >> 4, ee = o & 15;
        float accv = 0.f;
#pragma unroll
        for (int dd = 0; dd < 16; dd++)
            accv += proj_w[c * 256 + h * 16 + dd] * sA[dd * 16 + ee];
        __nv_bfloat16 hh, ll;
        split2(accv, hh, ll);
        g_Ah[aBase + c * 256 + h * 16 + ee] = hh;
        g_Al[aBase + c * 256 + h * 16 + ee] = ll;
    }
}

// ---------------- launch ----------------
extern "C" void kernel_launch(void* const* d_in, const int* in_sizes, int n_in,
                              void* d_out, int out_size)
{
    const float* x      = (const float*)d_in[0];
    const float* pos_w  = (const float*)d_in[1];
    const float* pos_b  = (const float*)d_in[2];
    const float* qd3_w  = (const float*)d_in[3];
    const float* qd3_b  = (const float*)d_in[4];
    const float* qd5_w  = (const float*)d_in[5];
    const float* qd5_b  = (const float*)d_in[6];
    const float* temp   = (const float*)d_in[7];
    const float* d3_w   = (const float*)d_in[8];
    const float* d3_b   = (const float*)d_in[9];
    const float* d5_w   = (const float*)d_in[10];
    const float* d5_b   = (const float*)d_in[11];
    const float* proj_w = (const float*)d_in[12];
    float* out = (float*)d_out;

    zero_gram_k<<<72, 256>>>();
    convert_x_k<<<16384, 256>>>(x);
    convert_w_k<<<48, 256>>>(pos_w);
    k1_gemm<<<dim3(256, 3, 8), 256>>>(pos_b);
    dualconv_k<0><<<dim3(4, 192, 8), 256>>>(nullptr, qd3_w, qd3_b, qd5_w, qd5_b);
    dualconv_k<1><<<dim3(4, 64, 8), 256>>>(x, d3_w, d3_b, d5_w, d5_b);
    gram_k<<<dim3(64, 16), 256>>>();
    attn_k<<<dim3(8, 9), 256>>>(temp, proj_w);
    k4_gemm<<<dim3(256, 1, 8), 256>>>(out);
}

// round 7
// speedup vs baseline: 1.3878x; 1.3878x over previous
#include <cuda_runtime.h>
#include <cuda_bf16.h>
#include <cstdint>

#define HW 16384
#define IMG 128

// ---------------- scratch (static __device__, no allocs) ----------------
__device__ float g_t[8L * 384 * HW];            // pos-conv output (B,384,H,W) fp32
__device__ float g_q[8L * 128 * HW];            // q channels fp32
__device__ float g_k[8L * 128 * HW];            // k channels fp32
__device__ __nv_bfloat16 g_xh[8L * 128 * HW];   // x split hi
__device__ __nv_bfloat16 g_xl[8L * 128 * HW];   // x split lo
__device__ __nv_bfloat16 g_yh[8L * 256 * HW];   // [v|d3|d5] split hi
__device__ __nv_bfloat16 g_yl[8L * 256 * HW];   // [v|d3|d5] split lo
__device__ __nv_bfloat16 g_wh[384 * 128];       // pos_w split hi
__device__ __nv_bfloat16 g_wl[384 * 128];       // pos_w split lo
__device__ __nv_bfloat16 g_Ah[8 * 128 * 256];   // folded proj*attn split hi
__device__ __nv_bfloat16 g_Al[8 * 128 * 256];   // folded proj*attn split lo
__device__ float g_gram[64 * 288];              // per (b,h): G[256], qn[16], kn[16]

__device__ __forceinline__ void split2(float v, __nv_bfloat16& h, __nv_bfloat16& l) {
    h = __float2bfloat16(v);
    l = __float2bfloat16(v - __bfloat162float(h));
}
__device__ __forceinline__ uint32_t smem_u32(const void* p) {
    uint32_t a;
    asm("{ .reg .u64 t; cvta.to.shared.u64 t, %1; cvt.u32.u64 %0, t; }" : "=r"(a) : "l"(p));
    return a;
}

// ---------------- zero gram accumulators ----------------
__global__ void zero_gram_k() {
    int i = blockIdx.x * 256 + threadIdx.x;
    if (i < 64 * 288) g_gram[i] = 0.f;
}

// ---------------- split conversions ----------------
__global__ void convert_x_k(const float* __restrict__ x) {
    long i = ((long)blockIdx.x * 256 + threadIdx.x) * 4;
    float4 v = *(const float4*)(x + i);
    __nv_bfloat16 h, l;
    split2(v.x, h, l); g_xh[i + 0] = h; g_xl[i + 0] = l;
    split2(v.y, h, l); g_xh[i + 1] = h; g_xl[i + 1] = l;
    split2(v.z, h, l); g_xh[i + 2] = h; g_xl[i + 2] = l;
    split2(v.w, h, l); g_xh[i + 3] = h; g_xl[i + 3] = l;
}
__global__ void convert_w_k(const float* __restrict__ w) {
    long i = ((long)blockIdx.x * 256 + threadIdx.x) * 4;
    float4 v = *(const float4*)(w + i);
    __nv_bfloat16 h, l;
    split2(v.x, h, l); g_wh[i + 0] = h; g_wl[i + 0] = l;
    split2(v.y, h, l); g_wh[i + 1] = h; g_wl[i + 1] = l;
    split2(v.z, h, l); g_wh[i + 2] = h; g_wl[i + 2] = l;
    split2(v.w, h, l); g_wh[i + 3] = h; g_wl[i + 3] = l;
}

// ---------------- mma.sync helpers ----------------
__device__ __forceinline__ void hmma(float* c, const uint32_t* a, uint32_t b0, uint32_t b1) {
    asm volatile(
        "mma.sync.aligned.m16n8k16.row.col.f32.bf16.bf16.f32 "
        "{%0,%1,%2,%3}, {%4,%5,%6,%7}, {%8,%9}, {%0,%1,%2,%3};"
        : "+f"(c[0]), "+f"(c[1]), "+f"(c[2]), "+f"(c[3])
        : "r"(a[0]), "r"(a[1]), "r"(a[2]), "r"(a[3]), "r"(b0), "r"(b1));
}
__device__ __forceinline__ void ldsm4(uint32_t* r, uint32_t addr) {
    asm volatile("ldmatrix.sync.aligned.m8n8.x4.shared.b16 {%0,%1,%2,%3}, [%4];"
        : "=r"(r[0]), "=r"(r[1]), "=r"(r[2]), "=r"(r[3]) : "r"(addr));
}
__device__ __forceinline__ void ldsm4t(uint32_t* r, uint32_t addr) {
    asm volatile("ldmatrix.sync.aligned.m8n8.x4.trans.shared.b16 {%0,%1,%2,%3}, [%4];"
        : "=r"(r[0]), "=r"(r[1]), "=r"(r[2]), "=r"(r[3]) : "r"(addr));
}

// ---------------- bf16-split GEMM, ldmatrix + mma.sync ----------------
// C[b](M x 16384) = (Ah+Al)(M x K) @ (Bh+Bl)(K x 16384), 3 terms, fp32 accum.
// CTA tile 128m x 128n, 8 warps (4m x 2n), warp tile 32x64, k64 smem stages.
// A smem: [128][72] padded (144B row stride, LDSM conflict-free).
// B smem: natural [k][n] [64][136] padded (272B stride, LDSM.trans conflict-free).
#define A_STRIDE 72
#define B_STRIDE 136
#define SM_A (128 * A_STRIDE * 2)      // bytes per A source
#define SM_B (64 * B_STRIDE * 2)       // bytes per B source
#define SM_TOTAL (2 * SM_A + 2 * SM_B) // 71680

template <int K>
__device__ __forceinline__ void mmasync_body(
    const __nv_bfloat16* __restrict__ Ah, const __nv_bfloat16* __restrict__ Al,
    long aStride,
    const __nv_bfloat16* __restrict__ Bh, const __nv_bfloat16* __restrict__ Bl,
    long bStride,
    float* __restrict__ C, long cStride, const float* __restrict__ bias)
{
    extern __shared__ char dsm[];
    __nv_bfloat16* AsH = (__nv_bfloat16*)dsm;
    __nv_bfloat16* AsL = (__nv_bfloat16*)(dsm + SM_A);
    __nv_bfloat16* BsH = (__nv_bfloat16*)(dsm + 2 * SM_A);
    __nv_bfloat16* BsL = (__nv_bfloat16*)(dsm + 2 * SM_A + SM_B);
    const uint32_t sbase = smem_u32(dsm);

    const int b = blockIdx.z;
    const int m0 = blockIdx.y * 128;
    const int n0 = blockIdx.x * 128;
    const int tid = threadIdx.x;
    const int wid = tid >> 5, lane = tid & 31;
    const int wm = (wid & 3) * 32, wn = (wid >> 2) * 64;
    const int g = lane >> 2, tq = lane & 3;
    const int lrow = lane & 15;              // ldmatrix lane row
    const int lcol = (lane >> 4) * 8;        // ldmatrix lane col half

    const __nv_bfloat16* AhB = Ah + (long)b * aStride;
    const __nv_bfloat16* AlB = Al + (long)b * aStride;
    const __nv_bfloat16* BhB = Bh + (long)b * bStride;
    const __nv_bfloat16* BlB = Bl + (long)b * bStride;

    float c[2][8][4];
#pragma unroll
    for (int mi = 0; mi < 2; mi++)
#pragma unroll
        for (int nb = 0; nb < 8; nb++)
#pragma unroll
            for (int j = 0; j < 4; j++) c[mi][nb][j] = 0.f;

    for (int ch = 0; ch < K / 64; ch++) {
        const int ko = ch * 64;
        // ---- global -> smem (coalesced uint4, natural layouts)
#pragma unroll
        for (int t = 0; t < 4; t++) {
            int idx = tid + t * 256;
            int row = idx >> 3, cc = (idx & 7) * 8;
            long go = (long)(m0 + row) * K + ko + cc;
            *(uint4*)(AsH + row * A_STRIDE + cc) = *(const uint4*)(AhB + go);
            *(uint4*)(AsL + row * A_STRIDE + cc) = *(const uint4*)(AlB + go);
        }
#pragma unroll
        for (int t = 0; t < 4; t++) {
            int idx = tid + t * 256;
            int row = idx >> 4, cc = (idx & 15) * 8;
            long go = (long)(ko + row) * HW + n0 + cc;
            *(uint4*)(BsH + row * B_STRIDE + cc) = *(const uint4*)(BhB + go);
            *(uint4*)(BsL + row * B_STRIDE + cc) = *(const uint4*)(BlB + go);
        }
        __syncthreads();

#pragma unroll
        for (int kc = 0; kc < 4; kc++) {
            uint32_t aH[2][4], aL[2][4];
#pragma unroll
            for (int mi = 0; mi < 2; mi++) {
                uint32_t ad = sbase +
                    (uint32_t)(((wm + mi * 16 + lrow) * A_STRIDE + kc * 16 + lcol) * 2);
                ldsm4(aH[mi], ad);
                ldsm4(aL[mi], ad + SM_A);
            }
#pragma unroll
            for (int nbp = 0; nbp < 4; nbp++) {
                uint32_t bd = sbase + (uint32_t)(2 * SM_A) +
                    (uint32_t)(((kc * 16 + lrow) * B_STRIDE + wn + nbp * 16 + lcol) * 2);
                uint32_t bH[4], bL[4];
                ldsm4t(bH, bd);
                ldsm4t(bL, bd + SM_B);
                int nb = nbp * 2;
#pragma unroll
                for (int mi = 0; mi < 2; mi++) {
                    hmma(c[mi][nb],     aH[mi], bH[0], bH[1]);
                    hmma(c[mi][nb],     aL[mi], bH[0], bH[1]);
                    hmma(c[mi][nb],     aH[mi], bL[0], bL[1]);
                    hmma(c[mi][nb + 1], aH[mi], bH[2], bH[3]);
                    hmma(c[mi][nb + 1], aL[mi], bH[2], bH[3]);
                    hmma(c[mi][nb + 1], aH[mi], bL[2], bL[3]);
                }
            }
        }
        __syncthreads();
    }

    // ---- epilogue
#pragma unroll
    for (int mi = 0; mi < 2; mi++) {
        int r0 = m0 + wm + mi * 16 + g;
        float bv0 = bias ? bias[r0] : 0.f;
        float bv1 = bias ? bias[r0 + 8] : 0.f;
#pragma unroll
        for (int nb = 0; nb < 8; nb++) {
            int col = n0 + wn + nb * 8 + tq * 2;
            float* p0 = C + (long)b * cStride + (long)r0 * HW + col;
            float* p1 = p0 + 8L * HW;
            *(float2*)p0 = make_float2(c[mi][nb][0] + bv0, c[mi][nb][1] + bv0);
            *(float2*)p1 = make_float2(c[mi][nb][2] + bv1, c[mi][nb][3] + bv1);
        }
    }
}

__global__ __launch_bounds__(256) void k1_gemm(const float* __restrict__ pb) {
    mmasync_body<128>(g_wh, g_wl, 0L, g_xh, g_xl, 128L * HW, g_t, 384L * HW, pb);
}
__global__ __launch_bounds__(256) void k4_gemm(float* __restrict__ out) {
    mmasync_body<256>(g_Ah, g_Al, 128L * 256, g_yh, g_yl, 256L * HW, out, 128L * HW, nullptr);
}

// ---------------- dual grouped conv (3x3 + 5x5 sharing input pair) ----------------
template <int MODE>
__global__ __launch_bounds__(256, 3) void dualconv_k(
    const float* __restrict__ in_ext,
    const float* __restrict__ w3, const float* __restrict__ b3,
    const float* __restrict__ w5, const float* __restrict__ b5)
{
    const int Cin = (MODE == 0) ? 384 : 128;
    const float* in = (MODE == 0) ? (const float*)g_t : in_ext;

    __shared__ float s[2 * 68 * 68];
    __shared__ float sw[68];

    const int tile = blockIdx.x;
    const int oy0 = (tile >> 1) * 64;
    const int ox0 = (tile & 1) * 64;
    const int g = blockIdx.y;
    const long bz = blockIdx.z;
    const int tid = threadIdx.x;
    const int ttx = tid & 15, tty = tid >> 4;
    const int py0 = tty * 4, px0 = ttx * 4;

    const float* in0 = in + (bz * Cin + 2 * g) * (long)HW;
    for (int idx = tid; idx < 2 * 68 * 68; idx += 256) {
        int ch = idx / 4624;
        int rem = idx - ch * 4624;
        int r = rem / 68, cc = rem - r * 68;
        int gy = oy0 - 2 + r, gx = ox0 - 2 + cc;
        float v = 0.f;
        if ((unsigned)gy < 128u && (unsigned)gx < 128u)
            v = in0[ch * HW + gy * IMG + gx];
        s[idx] = v;
    }
    if (tid < 50) sw[tid] = w5[g * 50 + tid];
    else if (tid < 68) sw[tid] = w3[g * 18 + (tid - 50)];
    __syncthreads();

    const float bias3 = b3[g], bias5 = b5[g];
    float* f3 = nullptr; long y3 = -1;
    float* f5 = nullptr; long y5 = -1;
    if (MODE == 0) {
        if (g < 128) f3 = &g_q[(bz * 128 + g) * HW];
        else         f3 = &g_k[(bz * 128 + (g - 128)) * HW];
        if (g < 64)  f5 = &g_k[(bz * 128 + 64 + g) * HW];
        else         y5 = (bz * 256 + (g - 64)) * HW;
    } else {
        y3 = (bz * 256 + 128 + g) * HW;
        y5 = (bz * 256 + 192 + g) * HW;
    }

#pragma unroll
    for (int half = 0; half < 2; half++) {
        float a3[2][4], a5[2][4];
#pragma unroll
        for (int i = 0; i < 2; i++)
#pragma unroll
            for (int j = 0; j < 4; j++) { a3[i][j] = 0.f; a5[i][j] = 0.f; }

#pragma unroll
        for (int ic = 0; ic < 2; ++ic) {
            const float* sc = s + ic * 4624 + (py0 + half * 2) * 68 + px0;
            float r[6][8];
#pragma unroll
            for (int dy = 0; dy < 6; dy++)
#pragma unroll
                for (int dx = 0; dx < 8; dx++) r[dy][dx] = sc[dy * 68 + dx];
            const float* w5s = sw + ic * 25;
#pragma unroll
            for (int t = 0; t < 25; t++) {
                float wv = w5s[t];
                int ky = t / 5, kx = t % 5;
#pragma unroll
                for (int oy = 0; oy < 2; oy++)
#pragma unroll
                    for (int ox = 0; ox < 4; ox++)
                        a5[oy][ox] += r[oy + ky][ox + kx] * wv;
            }
            const float* w3s = sw + 50 + ic * 9;
#pragma unroll
            for (int t = 0; t < 9; t++) {
                float wv = w3s[t];
                int ky = t / 3, kx = t % 3;
#pragma unroll
                for (int oy = 0; oy < 2; oy++)
#pragma unroll
                    for (int ox = 0; ox < 4; ox++)
                        a3[oy][ox] += r[oy + 1 + ky][ox + 1 + kx] * wv;
            }
        }

#pragma unroll
        for (int oy = 0; oy < 2; oy++) {
            int off = (oy0 + py0 + half * 2 + oy) * IMG + ox0 + px0;
#pragma unroll
            for (int ox = 0; ox < 4; ox++) {
                float v3 = a3[oy][ox] + bias3;
                float v5 = a5[oy][ox] + bias5;
                if (f3) f3[off + ox] = v3;
                else { __nv_bfloat16 h, l; split2(v3, h, l); g_yh[y3 + off + ox] = h; g_yl[y3 + off + ox] = l; }
                if (f5) f5[off + ox] = v5;
                else { __nv_bfloat16 h, l; split2(v5, h, l); g_yh[y5 + off + ox] = h; g_yl[y5 + off + ox] = l; }
            }
        }
    }
}

// ---------------- gram: per (b,h): G[16][16] = q @ k^T over pixels + sq norms ------
__global__ __launch_bounds__(256) void gram_k()
{
    const int bh = blockIdx.x;
    const int slice = blockIdx.y;
    const int b = bh >> 3, h = bh & 7;
    const float* qp = g_q + (long)(b * 128 + h * 16) * HW + slice * 1024;
    const float* kp = g_k + (long)(b * 128 + h * 16) * HW + slice * 1024;

    __shared__ float sq[64][17];
    __shared__ float sk[64][17];
    const int tid = threadIdx.x;
    const int phase = tid & 15, dg = (tid >> 4) & 3, eg = tid >> 6;

    float acc[4][4], aq[4], ak[4];
#pragma unroll
    for (int i = 0; i < 4; i++) {
        aq[i] = 0.f; ak[i] = 0.f;
#pragma unroll
        for (int j = 0; j < 4; j++) acc[i][j] = 0.f;
    }

    for (int blk = 0; blk < 16; ++blk) {
        for (int idx = tid; idx < 1024; idx += 256) {
            int d = idx >> 6, p = idx & 63;
            sq[p][d] = qp[(long)d * HW + blk * 64 + p];
            sk[p][d] = kp[(long)d * HW + blk * 64 + p];
        }
        __syncthreads();
        for (int p = phase; p < 64; p += 16) {
            float qv[4], kv[4];
#pragma unroll
            for (int i = 0; i < 4; i++) qv[i] = sq[p][dg * 4 + i];
#pragma unroll
            for (int j = 0; j < 4; j++) kv[j] = sk[p][eg * 4 + j];
#pragma unroll
            for (int i = 0; i < 4; i++)
#pragma unroll
                for (int j = 0; j < 4; j++) acc[i][j] += qv[i] * kv[j];
            if (eg == 0) {
#pragma unroll
                for (int i = 0; i < 4; i++) aq[i] += qv[i] * qv[i];
            }
            if (dg == 0) {
#pragma unroll
                for (int j = 0; j < 4; j++) ak[j] += kv[j] * kv[j];
            }
        }
        __syncthreads();
    }

    __shared__ float sG[288];
    for (int idx = tid; idx < 288; idx += 256) sG[idx] = 0.f;
    __syncthreads();
#pragma unroll
    for (int i = 0; i < 4; i++)
#pragma unroll
        for (int j = 0; j < 4; j++)
            atomicAdd(&sG[(dg * 4 + i) * 16 + eg * 4 + j], acc[i][j]);
    if (eg == 0) {
#pragma unroll
        for (int i = 0; i < 4; i++) atomicAdd(&sG[256 + dg * 4 + i], aq[i]);
    }
    if (dg == 0) {
#pragma unroll
        for (int j = 0; j < 4; j++) atomicAdd(&sG[272 + eg * 4 + j], ak[j]);
    }
    __syncthreads();
    float* gg = g_gram + bh * 288;
    for (int idx = tid; idx < 288; idx += 256) atomicAdd(gg + idx, sG[idx]);
}

// ---------------- attn: normalize gram, softmax, fold with proj into A (bf16 split) --
__global__ __launch_bounds__(256) void attn_k(
    const float* __restrict__ temp, const float* __restrict__ proj_w)
{
    const int b = blockIdx.x;
    const int part = blockIdx.y;
    const int tid = threadIdx.x;
    const long aBase = (long)b * 128 * 256;

    if (part == 8) {
        for (int idx = tid; idx < 128 * 128; idx += 256) {
            int c = idx >> 7, j = idx & 127;
            __nv_bfloat16 h, l;
            split2(proj_w[c * 256 + 128 + j], h, l);
            g_Ah[aBase + c * 256 + 128 + j] = h;
            g_Al[aBase + c * 256 + 128 + j] = l;
        }
        return;
    }
    const int h = part;
    const float* gg = g_gram + (b * 8 + h) * 288;
    __shared__ float sA[256], sqn[16], skn[16], srm[16], srs[16];
    if (tid < 16) {
        sqn[tid] = fmaxf(sqrtf(gg[256 + tid]), 1e-12f);
        skn[tid] = fmaxf(sqrtf(gg[272 + tid]), 1e-12f);
    }
    __syncthreads();
    const int d = tid >> 4, e = tid & 15;
    float val = gg[d * 16 + e] / (sqn[d] * skn[e]) * temp[h];
    sA[tid] = val;
    __syncthreads();
    if (e == 0) {
        float m = -1e30f;
        for (int j = 0; j < 16; j++) m = fmaxf(m, sA[d * 16 + j]);
        srm[d] = m;
    }
    __syncthreads();
    float p = expf(val - srm[d]);
    sA[tid] = p;
    __syncthreads();
    if (e == 0) {
        float ssum = 0.f;
        for (int j = 0; j < 16; j++) ssum += sA[d * 16 + j];
        srs[d] = ssum;
    }
    __syncthreads();
    sA[tid] = p / srs[d];
    __syncthreads();
    for (int o = tid; o < 2048; o += 256) {
        int c = o >> 4, ee = o & 15;
        float accv = 0.f;
#pragma unroll
        for (int dd = 0; dd < 16; dd++)
            accv += proj_w[c * 256 + h * 16 + dd] * sA[dd * 16 + ee];
        __nv_bfloat16 hh, ll;
        split2(accv, hh, ll);
        g_Ah[aBase + c * 256 + h * 16 + ee] = hh;
        g_Al[aBase + c * 256 + h * 16 + ee] = ll;
    }
}

// ---------------- launch ----------------
extern "C" void kernel_launch(void* const* d_in, const int* in_sizes, int n_in,
                              void* d_out, int out_size)
{
    const float* x      = (const float*)d_in[0];
    const float* pos_w  = (const float*)d_in[1];
    const float* pos_b  = (const float*)d_in[2];
    const float* qd3_w  = (const float*)d_in[3];
    const float* qd3_b  = (const float*)d_in[4];
    const float* qd5_w  = (const float*)d_in[5];
    const float* qd5_b  = (const float*)d_in[6];
    const float* temp   = (const float*)d_in[7];
    const float* d3_w   = (const float*)d_in[8];
    const float* d3_b   = (const float*)d_in[9];
    const float* d5_w   = (const float*)d_in[10];
    const float* d5_b   = (const float*)d_in[11];
    const float* proj_w = (const float*)d_in[12];
    float* out = (float*)d_out;

    static bool attr_done = false;
    if (!attr_done) {
        cudaFuncSetAttribute(k1_gemm, cudaFuncAttributeMaxDynamicSharedMemorySize, SM_TOTAL);
        cudaFuncSetAttribute(k4_gemm, cudaFuncAttributeMaxDynamicSharedMemorySize, SM_TOTAL);
        attr_done = true;
    }

    zero_gram_k<<<72, 256>>>();
    convert_x_k<<<16384, 256>>>(x);
    convert_w_k<<<48, 256>>>(pos_w);
    k1_gemm<<<dim3(128, 3, 8), 256, SM_TOTAL>>>(pos_b);
    dualconv_k<0><<<dim3(4, 192, 8), 256>>>(nullptr, qd3_w, qd3_b, qd5_w, qd5_b);
    dualconv_k<1><<<dim3(4, 64, 8), 256>>>(x, d3_w, d3_b, d5_w, d5_b);
    gram_k<<<dim3(64, 16), 256>>>();
    attn_k<<<dim3(8, 9), 256>>>(temp, proj_w);
    k4_gemm<<<dim3(128, 1, 8), 256, SM_TOTAL>>>(out);
}

// round 10
// speedup vs baseline: 1.4027x; 1.0107x over previous
#include <cuda_runtime.h>
#include <cuda_bf16.h>
#include <cstdint>

#define HW 16384
#define IMG 128

// ---------------- scratch (static __device__, no allocs) ----------------
__device__ float g_t[8L * 384 * HW];            // pos-conv output (B,384,H,W) fp32
__device__ float g_q[8L * 128 * HW];            // q channels fp32
__device__ float g_k[8L * 128 * HW];            // k channels fp32
__device__ __nv_bfloat16 g_xh[8L * 128 * HW];   // x split hi
__device__ __nv_bfloat16 g_xl[8L * 128 * HW];   // x split lo
__device__ __nv_bfloat16 g_yh[8L * 256 * HW];   // [v|d3|d5] split hi
__device__ __nv_bfloat16 g_yl[8L * 256 * HW];   // [v|d3|d5] split lo
__device__ __nv_bfloat16 g_wh[384 * 128];       // pos_w split hi
__device__ __nv_bfloat16 g_wl[384 * 128];       // pos_w split lo
__device__ __nv_bfloat16 g_Ah[8 * 128 * 256];   // folded proj*attn split hi
__device__ __nv_bfloat16 g_Al[8 * 128 * 256];   // folded proj*attn split lo
__device__ float g_gram[64 * 288];              // per (b,h): G[256], qn[16], kn[16]

__device__ __forceinline__ void split2(float v, __nv_bfloat16& h, __nv_bfloat16& l) {
    h = __float2bfloat16(v);
    l = __float2bfloat16(v - __bfloat162float(h));
}
__device__ __forceinline__ uint32_t smem_u32(const void* p) {
    uint32_t a;
    asm("{ .reg .u64 t; cvta.to.shared.u64 t, %1; cvt.u32.u64 %0, t; }" : "=r"(a) : "l"(p));
    return a;
}

// ---------------- zero gram accumulators ----------------
__global__ void zero_gram_k() {
    int i = blockIdx.x * 256 + threadIdx.x;
    if (i < 64 * 288) g_gram[i] = 0.f;
}

// ---------------- split conversions ----------------
__global__ void convert_x_k(const float* __restrict__ x) {
    long i = ((long)blockIdx.x * 256 + threadIdx.x) * 4;
    float4 v = *(const float4*)(x + i);
    __nv_bfloat16 h, l;
    split2(v.x, h, l); g_xh[i + 0] = h; g_xl[i + 0] = l;
    split2(v.y, h, l); g_xh[i + 1] = h; g_xl[i + 1] = l;
    split2(v.z, h, l); g_xh[i + 2] = h; g_xl[i + 2] = l;
    split2(v.w, h, l); g_xh[i + 3] = h; g_xl[i + 3] = l;
}
__global__ void convert_w_k(const float* __restrict__ w) {
    long i = ((long)blockIdx.x * 256 + threadIdx.x) * 4;
    float4 v = *(const float4*)(w + i);
    __nv_bfloat16 h, l;
    split2(v.x, h, l); g_wh[i + 0] = h; g_wl[i + 0] = l;
    split2(v.y, h, l); g_wh[i + 1] = h; g_wl[i + 1] = l;
    split2(v.z, h, l); g_wh[i + 2] = h; g_wl[i + 2] = l;
    split2(v.w, h, l); g_wh[i + 3] = h; g_wl[i + 3] = l;
}

// ---------------- mma.sync helpers ----------------
__device__ __forceinline__ void hmma(float* c, const uint32_t* a, uint32_t b0, uint32_t b1) {
    asm volatile(
        "mma.sync.aligned.m16n8k16.row.col.f32.bf16.bf16.f32 "
        "{%0,%1,%2,%3}, {%4,%5,%6,%7}, {%8,%9}, {%0,%1,%2,%3};"
        : "+f"(c[0]), "+f"(c[1]), "+f"(c[2]), "+f"(c[3])
        : "r"(a[0]), "r"(a[1]), "r"(a[2]), "r"(a[3]), "r"(b0), "r"(b1));
}
__device__ __forceinline__ void ldsm4(uint32_t* r, uint32_t addr) {
    asm volatile("ldmatrix.sync.aligned.m8n8.x4.shared.b16 {%0,%1,%2,%3}, [%4];"
        : "=r"(r[0]), "=r"(r[1]), "=r"(r[2]), "=r"(r[3]) : "r"(addr));
}
__device__ __forceinline__ void ldsm4t(uint32_t* r, uint32_t addr) {
    asm volatile("ldmatrix.sync.aligned.m8n8.x4.trans.shared.b16 {%0,%1,%2,%3}, [%4];"
        : "=r"(r[0]), "=r"(r[1]), "=r"(r[2]), "=r"(r[3]) : "r"(addr));
}

// ---------------- bf16-split GEMM, 128-thread CTAs for co-residency ----------------
// C[b](M x 16384) = (Ah+Al)(M x K) @ (Bh+Bl)(K x 16384), 3 terms, fp32 accum.
// CTA tile 64m x 128n, 4 warps (2m x 2n), warp tile 32x64, k32 smem chunks.
// ~27.6KB static smem, ~140 regs -> 3 CTAs/SM: loads of one CTA overlap
// compute of the others (no cp.async — convicted by R8/R9 container failures).
#define A_STRIDE 40
#define B_STRIDE 136

template <int K>
__device__ __forceinline__ void mmasync_body(
    const __nv_bfloat16* __restrict__ Ah, const __nv_bfloat16* __restrict__ Al,
    long aStride,
    const __nv_bfloat16* __restrict__ Bh, const __nv_bfloat16* __restrict__ Bl,
    long bStride,
    float* __restrict__ C, long cStride, const float* __restrict__ bias)
{
    __shared__ __nv_bfloat16 sAH[64 * A_STRIDE];
    __shared__ __nv_bfloat16 sAL[64 * A_STRIDE];
    __shared__ __nv_bfloat16 sBH[32 * B_STRIDE];
    __shared__ __nv_bfloat16 sBL[32 * B_STRIDE];
    const uint32_t uAH = smem_u32(sAH), uAL = smem_u32(sAL);
    const uint32_t uBH = smem_u32(sBH), uBL = smem_u32(sBL);

    const int b = blockIdx.z;
    const int m0 = blockIdx.y * 64;
    const int n0 = blockIdx.x * 128;
    const int tid = threadIdx.x;
    const int wid = tid >> 5, lane = tid & 31;
    const int wm = (wid & 1) * 32, wn = (wid >> 1) * 64;
    const int g = lane >> 2, tq = lane & 3;
    const int lrow = lane & 15;
    const int lcol = (lane >> 4) * 8;

    const __nv_bfloat16* AhB = Ah + (long)b * aStride;
    const __nv_bfloat16* AlB = Al + (long)b * aStride;
    const __nv_bfloat16* BhB = Bh + (long)b * bStride;
    const __nv_bfloat16* BlB = Bl + (long)b * bStride;

    // load indices: A 64x32 (256 uint4/src), B 32x128 (512 uint4/src), 128 thr
    const int ar = tid >> 2, ac = (tid & 3) * 8;     // A: 2 passes of 32... (idx>>2 up to 63)
    const int br4 = tid >> 4, bc4 = (tid & 15) * 8;  // B: 4 passes of 8 rows

    float c[2][8][4];
#pragma unroll
    for (int mi = 0; mi < 2; mi++)
#pragma unroll
        for (int nb = 0; nb < 8; nb++)
#pragma unroll
            for (int j = 0; j < 4; j++) c[mi][nb][j] = 0.f;

    const int NC = K / 32;
    for (int ch = 0; ch < NC; ch++) {
        const int ko = ch * 32;
        // A: idx 0..255 per source -> row = idx>>2 (0..63), col8 = (idx&3)*8
#pragma unroll
        for (int p = 0; p < 2; p++) {
            int row = ar + p * 32;
            long go = (long)(m0 + row) * K + ko + ac;
            *(uint4*)(sAH + row * A_STRIDE + ac) = *(const uint4*)(AhB + go);
            *(uint4*)(sAL + row * A_STRIDE + ac) = *(const uint4*)(AlB + go);
        }
        // B: idx 0..511 per source -> row = idx>>4 (0..31), col = (idx&15)*8
#pragma unroll
        for (int p = 0; p < 4; p++) {
            int row = br4 + p * 8;
            long go = (long)(ko + row) * HW + n0 + bc4;
            *(uint4*)(sBH + row * B_STRIDE + bc4) = *(const uint4*)(BhB + go);
            *(uint4*)(sBL + row * B_STRIDE + bc4) = *(const uint4*)(BlB + go);
        }
        __syncthreads();

#pragma unroll
        for (int kc = 0; kc < 2; kc++) {
            uint32_t aH[2][4], aL[2][4];
#pragma unroll
            for (int mi = 0; mi < 2; mi++) {
                uint32_t off = (uint32_t)(((wm + mi * 16 + lrow) * A_STRIDE + kc * 16 + lcol) * 2);
                ldsm4(aH[mi], uAH + off);
                ldsm4(aL[mi], uAL + off);
            }
#pragma unroll
            for (int nbp = 0; nbp < 4; nbp++) {
                uint32_t off = (uint32_t)(((kc * 16 + lrow) * B_STRIDE + wn + nbp * 16 + lcol) * 2);
                uint32_t bH[4], bL[4];
                ldsm4t(bH, uBH + off);
                ldsm4t(bL, uBL + off);
                int nb = nbp * 2;
                // term-major: consecutive HMMAs hit distinct accumulators
#pragma unroll
                for (int t = 0; t < 3; t++) {
                    const uint32_t (*af)[4] = (t == 1) ? aL : aH;
                    const uint32_t* bf = (t == 2) ? bL : bH;
#pragma unroll
                    for (int mi = 0; mi < 2; mi++) {
                        hmma(c[mi][nb],     af[mi], bf[0], bf[1]);
                        hmma(c[mi][nb + 1], af[mi], bf[2], bf[3]);
                    }
                }
            }
        }
        __syncthreads();
    }

    // ---- epilogue
#pragma unroll
    for (int mi = 0; mi < 2; mi++) {
        int r0 = m0 + wm + mi * 16 + g;
        float bv0 = bias ? bias[r0] : 0.f;
        float bv1 = bias ? bias[r0 + 8] : 0.f;
#pragma unroll
        for (int nb = 0; nb < 8; nb++) {
            int col = n0 + wn + nb * 8 + tq * 2;
            float* p0 = C + (long)b * cStride + (long)r0 * HW + col;
            float* p1 = p0 + 8L * HW;
            *(float2*)p0 = make_float2(c[mi][nb][0] + bv0, c[mi][nb][1] + bv0);
            *(float2*)p1 = make_float2(c[mi][nb][2] + bv1, c[mi][nb][3] + bv1);
        }
    }
}

__global__ __launch_bounds__(128) void k1_gemm(const float* __restrict__ pb) {
    mmasync_body<128>(g_wh, g_wl, 0L, g_xh, g_xl, 128L * HW, g_t, 384L * HW, pb);
}
__global__ __launch_bounds__(128) void k4_gemm(float* __restrict__ out) {
    mmasync_body<256>(g_Ah, g_Al, 128L * 256, g_yh, g_yl, 256L * HW, out, 128L * HW, nullptr);
}

// ---------------- dual grouped conv (3x3 + 5x5 sharing input pair) ----------------
template <int MODE>
__global__ __launch_bounds__(256, 3) void dualconv_k(
    const float* __restrict__ in_ext,
    const float* __restrict__ w3, const float* __restrict__ b3,
    const float* __restrict__ w5, const float* __restrict__ b5)
{
    const int Cin = (MODE == 0) ? 384 : 128;
    const float* in = (MODE == 0) ? (const float*)g_t : in_ext;

    __shared__ float s[2 * 68 * 68];
    __shared__ float sw[68];

    const int tile = blockIdx.x;
    const int oy0 = (tile >> 1) * 64;
    const int ox0 = (tile & 1) * 64;
    const int g = blockIdx.y;
    const long bz = blockIdx.z;
    const int tid = threadIdx.x;
    const int ttx = tid & 15, tty = tid >> 4;
    const int py0 = tty * 4, px0 = ttx * 4;

    const float* in0 = in + (bz * Cin + 2 * g) * (long)HW;
    for (int idx = tid; idx < 2 * 68 * 68; idx += 256) {
        int ch = idx / 4624;
        int rem = idx - ch * 4624;
        int r = rem / 68, cc = rem - r * 68;
        int gy = oy0 - 2 + r, gx = ox0 - 2 + cc;
        float v = 0.f;
        if ((unsigned)gy < 128u && (unsigned)gx < 128u)
            v = in0[ch * HW + gy * IMG + gx];
        s[idx] = v;
    }
    if (tid < 50) sw[tid] = w5[g * 50 + tid];
    else if (tid < 68) sw[tid] = w3[g * 18 + (tid - 50)];
    __syncthreads();

    const float bias3 = b3[g], bias5 = b5[g];
    float* f3 = nullptr; long y3 = -1;
    float* f5 = nullptr; long y5 = -1;
    if (MODE == 0) {
        if (g < 128) f3 = &g_q[(bz * 128 + g) * HW];
        else         f3 = &g_k[(bz * 128 + (g - 128)) * HW];
        if (g < 64)  f5 = &g_k[(bz * 128 + 64 + g) * HW];
        else         y5 = (bz * 256 + (g - 64)) * HW;
    } else {
        y3 = (bz * 256 + 128 + g) * HW;
        y5 = (bz * 256 + 192 + g) * HW;
    }

#pragma unroll
    for (int half = 0; half < 2; half++) {
        float a3[2][4], a5[2][4];
#pragma unroll
        for (int i = 0; i < 2; i++)
#pragma unroll
            for (int j = 0; j < 4; j++) { a3[i][j] = 0.f; a5[i][j] = 0.f; }

#pragma unroll
        for (int ic = 0; ic < 2; ++ic) {
            const float* sc = s + ic * 4624 + (py0 + half * 2) * 68 + px0;
            float r[6][8];
#pragma unroll
            for (int dy = 0; dy < 6; dy++)
#pragma unroll
                for (int dx = 0; dx < 8; dx++) r[dy][dx] = sc[dy * 68 + dx];
            const float* w5s = sw + ic * 25;
#pragma unroll
            for (int t = 0; t < 25; t++) {
                float wv = w5s[t];
                int ky = t / 5, kx = t % 5;
#pragma unroll
                for (int oy = 0; oy < 2; oy++)
#pragma unroll
                    for (int ox = 0; ox < 4; ox++)
                        a5[oy][ox] += r[oy + ky][ox + kx] * wv;
            }
            const float* w3s = sw + 50 + ic * 9;
#pragma unroll
            for (int t = 0; t < 9; t++) {
                float wv = w3s[t];
                int ky = t / 3, kx = t % 3;
#pragma unroll
                for (int oy = 0; oy < 2; oy++)
#pragma unroll
                    for (int ox = 0; ox < 4; ox++)
                        a3[oy][ox] += r[oy + 1 + ky][ox + 1 + kx] * wv;
            }
        }

#pragma unroll
        for (int oy = 0; oy < 2; oy++) {
            int off = (oy0 + py0 + half * 2 + oy) * IMG + ox0 + px0;
#pragma unroll
            for (int ox = 0; ox < 4; ox++) {
                float v3 = a3[oy][ox] + bias3;
                float v5 = a5[oy][ox] + bias5;
                if (f3) f3[off + ox] = v3;
                else { __nv_bfloat16 h, l; split2(v3, h, l); g_yh[y3 + off + ox] = h; g_yl[y3 + off + ox] = l; }
                if (f5) f5[off + ox] = v5;
                else { __nv_bfloat16 h, l; split2(v5, h, l); g_yh[y5 + off + ox] = h; g_yl[y5 + off + ox] = l; }
            }
        }
    }
}

// ---------------- gram: per (b,h): G[16][16] = q @ k^T over pixels + sq norms ------
__global__ __launch_bounds__(256) void gram_k()
{
    const int bh = blockIdx.x;
    const int slice = blockIdx.y;
    const int b = bh >> 3, h = bh & 7;
    const float* qp = g_q + (long)(b * 128 + h * 16) * HW + slice * 1024;
    const float* kp = g_k + (long)(b * 128 + h * 16) * HW + slice * 1024;

    __shared__ float sq[64][17];
    __shared__ float sk[64][17];
    const int tid = threadIdx.x;
    const int phase = tid & 15, dg = (tid >> 4) & 3, eg = tid >> 6;

    float acc[4][4], aq[4], ak[4];
#pragma unroll
    for (int i = 0; i < 4; i++) {
        aq[i] = 0.f; ak[i] = 0.f;
#pragma unroll
        for (int j = 0; j < 4; j++) acc[i][j] = 0.f;
    }

    for (int blk = 0; blk < 16; ++blk) {
        for (int idx = tid; idx < 1024; idx += 256) {
            int d = idx >> 6, p = idx & 63;
            sq[p][d] = qp[(long)d * HW + blk * 64 + p];
            sk[p][d] = kp[(long)d * HW + blk * 64 + p];
        }
        __syncthreads();
        for (int p = phase; p < 64; p += 16) {
            float qv[4], kv[4];
#pragma unroll
            for (int i = 0; i < 4; i++) qv[i] = sq[p][dg * 4 + i];
#pragma unroll
            for (int j = 0; j < 4; j++) kv[j] = sk[p][eg * 4 + j];
#pragma unroll
            for (int i = 0; i < 4; i++)
#pragma unroll
                for (int j = 0; j < 4; j++) acc[i][j] += qv[i] * kv[j];
            if (eg == 0) {
#pragma unroll
                for (int i = 0; i < 4; i++) aq[i] += qv[i] * qv[i];
            }
            if (dg == 0) {
#pragma unroll
                for (int j = 0; j < 4; j++) ak[j] += kv[j] * kv[j];
            }
        }
        __syncthreads();
    }

    __shared__ float sG[288];
    for (int idx = tid; idx < 288; idx += 256) sG[idx] = 0.f;
    __syncthreads();
#pragma unroll
    for (int i = 0; i < 4; i++)
#pragma unroll
        for (int j = 0; j < 4; j++)
            atomicAdd(&sG[(dg * 4 + i) * 16 + eg * 4 + j], acc[i][j]);
    if (eg == 0) {
#pragma unroll
        for (int i = 0; i < 4; i++) atomicAdd(&sG[256 + dg * 4 + i], aq[i]);
    }
    if (dg == 0) {
#pragma unroll
        for (int j = 0; j < 4; j++) atomicAdd(&sG[272 + eg * 4 + j], ak[j]);
    }
    __syncthreads();
    float* gg = g_gram + bh * 288;
    for (int idx = tid; idx < 288; idx += 256) atomicAdd(gg + idx, sG[idx]);
}

// ---------------- attn: normalize gram, softmax, fold with proj into A (bf16 split) --
__global__ __launch_bounds__(256) void attn_k(
    const float* __restrict__ temp, const float* __restrict__ proj_w)
{
    const int b = blockIdx.x;
    const int part = blockIdx.y;
    const int tid = threadIdx.x;
    const long aBase = (long)b * 128 * 256;

    if (part == 8) {
        for (int idx = tid; idx < 128 * 128; idx += 256) {
            int c = idx >> 7, j = idx & 127;
            __nv_bfloat16 h, l;
            split2(proj_w[c * 256 + 128 + j], h, l);
            g_Ah[aBase + c * 256 + 128 + j] = h;
            g_Al[aBase + c * 256 + 128 + j] = l;
        }
        return;
    }
    const int h = part;
    const float* gg = g_gram + (b * 8 + h) * 288;
    __shared__ float sA[256], sqn[16], skn[16], srm[16], srs[16];
    if (tid < 16) {
        sqn[tid] = fmaxf(sqrtf(gg[256 + tid]), 1e-12f);
        skn[tid] = fmaxf(sqrtf(gg[272 + tid]), 1e-12f);
    }
    __syncthreads();
    const int d = tid >> 4, e = tid & 15;
    float val = gg[d * 16 + e] / (sqn[d] * skn[e]) * temp[h];
    sA[tid] = val;
    __syncthreads();
    if (e == 0) {
        float m = -1e30f;
        for (int j = 0; j < 16; j++) m = fmaxf(m, sA[d * 16 + j]);
        srm[d] = m;
    }
    __syncthreads();
    float p = expf(val - srm[d]);
    sA[tid] = p;
    __syncthreads();
    if (e == 0) {
        float ssum = 0.f;
        for (int j = 0; j < 16; j++) ssum += sA[d * 16 + j];
        srs[d] = ssum;
    }
    __syncthreads();
    sA[tid] = p / srs[d];
    __syncthreads();
    for (int o = tid; o < 2048; o += 256) {
        int c = o >> 4, ee = o & 15;
        float accv = 0.f;
#pragma unroll
        for (int dd = 0; dd < 16; dd++)
            accv += proj_w[c * 256 + h * 16 + dd] * sA[dd * 16 + ee];
        __nv_bfloat16 hh, ll;
        split2(accv, hh, ll);
        g_Ah[aBase + c * 256 + h * 16 + ee] = hh;
        g_Al[aBase + c * 256 + h * 16 + ee] = ll;
    }
}

// ---------------- launch ----------------
extern "C" void kernel_launch(void* const* d_in, const int* in_sizes, int n_in,
                              void* d_out, int out_size)
{
    const float* x      = (const float*)d_in[0];
    const float* pos_w  = (const float*)d_in[1];
    const float* pos_b  = (const float*)d_in[2];
    const float* qd3_w  = (const float*)d_in[3];
    const float* qd3_b  = (const float*)d_in[4];
    const float* qd5_w  = (const float*)d_in[5];
    const float* qd5_b  = (const float*)d_in[6];
    const float* temp   = (const float*)d_in[7];
    const float* d3_w   = (const float*)d_in[8];
    const float* d3_b   = (const float*)d_in[9];
    const float* d5_w   = (const float*)d_in[10];
    const float* d5_b   = (const float*)d_in[11];
    const float* proj_w = (const float*)d_in[12];
    float* out = (float*)d_out;

    zero_gram_k<<<72, 256>>>();
    convert_x_k<<<16384, 256>>>(x);
    convert_w_k<<<48, 256>>>(pos_w);
    k1_gemm<<<dim3(128, 6, 8), 128>>>(pos_b);
    dualconv_k<0><<<dim3(4, 192, 8), 256>>>(nullptr, qd3_w, qd3_b, qd5_w, qd5_b);
    dualconv_k<1><<<dim3(4, 64, 8), 256>>>(x, d3_w, d3_b, d5_w, d5_b);
    gram_k<<<dim3(64, 16), 256>>>();
    attn_k<<<dim3(8, 9), 256>>>(temp, proj_w);
    k4_gemm<<<dim3(128, 2, 8), 128>>>(out);
}

// round 11
// speedup vs baseline: 1.5190x; 1.0829x over previous
#include <cuda_runtime.h>
#include <cuda_bf16.h>
#include <cstdint>

#define HW 16384
#define IMG 128

// ---------------- scratch (static __device__, no allocs) ----------------
__device__ float g_t[8L * 384 * HW];            // pos-conv output (B,384,H,W) fp32
__device__ float g_q[8L * 128 * HW];            // q channels fp32
__device__ float g_k[8L * 128 * HW];            // k channels fp32
__device__ __nv_bfloat16 g_yh[8L * 256 * HW];   // [v|d3|d5] split hi
__device__ __nv_bfloat16 g_yl[8L * 256 * HW];   // [v|d3|d5] split lo
__device__ __nv_bfloat16 g_wh[384 * 128];       // pos_w split hi
__device__ __nv_bfloat16 g_wl[384 * 128];       // pos_w split lo
__device__ __nv_bfloat16 g_Ah[8 * 128 * 256];   // folded proj*attn split hi
__device__ __nv_bfloat16 g_Al[8 * 128 * 256];   // folded proj*attn split lo
__device__ float g_gram[64 * 288];              // per (b,h): G[256], qn[16], kn[16]

__device__ __forceinline__ void split2(float v, __nv_bfloat16& h, __nv_bfloat16& l) {
    h = __float2bfloat16(v);
    l = __float2bfloat16(v - __bfloat162float(h));
}
__device__ __forceinline__ uint32_t smem_u32(const void* p) {
    uint32_t a;
    asm("{ .reg .u64 t; cvta.to.shared.u64 t, %1; cvt.u32.u64 %0, t; }" : "=r"(a) : "l"(p));
    return a;
}
__device__ __forceinline__ uint32_t pack_bf2(__nv_bfloat16 a, __nv_bfloat16 b) {
    return (uint32_t)__bfloat16_as_ushort(a) | ((uint32_t)__bfloat16_as_ushort(b) << 16);
}

// ---------------- zero gram accumulators ----------------
__global__ void zero_gram_k() {
    int i = blockIdx.x * 256 + threadIdx.x;
    if (i < 64 * 288) g_gram[i] = 0.f;
}

// ---------------- split conversion for pos_w ----------------
__global__ void convert_w_k(const float* __restrict__ w) {
    long i = ((long)blockIdx.x * 256 + threadIdx.x) * 4;
    float4 v = *(const float4*)(w + i);
    __nv_bfloat16 h, l;
    split2(v.x, h, l); g_wh[i + 0] = h; g_wl[i + 0] = l;
    split2(v.y, h, l); g_wh[i + 1] = h; g_wl[i + 1] = l;
    split2(v.z, h, l); g_wh[i + 2] = h; g_wl[i + 2] = l;
    split2(v.w, h, l); g_wh[i + 3] = h; g_wl[i + 3] = l;
}

// ---------------- mma.sync helpers ----------------
__device__ __forceinline__ void hmma(float* c, const uint32_t* a, uint32_t b0, uint32_t b1) {
    asm volatile(
        "mma.sync.aligned.m16n8k16.row.col.f32.bf16.bf16.f32 "
        "{%0,%1,%2,%3}, {%4,%5,%6,%7}, {%8,%9}, {%0,%1,%2,%3};"
        : "+f"(c[0]), "+f"(c[1]), "+f"(c[2]), "+f"(c[3])
        : "r"(a[0]), "r"(a[1]), "r"(a[2]), "r"(a[3]), "r"(b0), "r"(b1));
}
__device__ __forceinline__ void ldsm4(uint32_t* r, uint32_t addr) {
    asm volatile("ldmatrix.sync.aligned.m8n8.x4.shared.b16 {%0,%1,%2,%3}, [%4];"
        : "=r"(r[0]), "=r"(r[1]), "=r"(r[2]), "=r"(r[3]) : "r"(addr));
}
__device__ __forceinline__ void ldsm4t(uint32_t* r, uint32_t addr) {
    asm volatile("ldmatrix.sync.aligned.m8n8.x4.trans.shared.b16 {%0,%1,%2,%3}, [%4];"
        : "=r"(r[0]), "=r"(r[1]), "=r"(r[2]), "=r"(r[3]) : "r"(addr));
}

// ---------------- bf16-split GEMM, register double-buffered ----------------
// C[b](M x 16384) = (Ah+Al)(M x K) @ B(K x 16384), 3 terms, fp32 accum.
// BSPLIT: B given as bf16 hi/lo pair. !BSPLIT: B given fp32, split in-regs (k1).
// CTA tile 64m x 128n, 4 warps (2m x 2n), k32 chunks, LDG->regs prefetch of
// chunk ch+1 overlapped with compute of chunk ch (no cp.async).
#define A_STRIDE 40
#define B_STRIDE 136

template <int K, bool BSPLIT>
__device__ __forceinline__ void mmasync_body(
    const __nv_bfloat16* __restrict__ Ah, const __nv_bfloat16* __restrict__ Al,
    long aStride,
    const __nv_bfloat16* __restrict__ Bh, const __nv_bfloat16* __restrict__ Bl,
    const float* __restrict__ Bf, long bStride,
    float* __restrict__ C, long cStride, const float* __restrict__ bias)
{
    __shared__ __nv_bfloat16 sAH[64 * A_STRIDE];
    __shared__ __nv_bfloat16 sAL[64 * A_STRIDE];
    __shared__ __nv_bfloat16 sBH[32 * B_STRIDE];
    __shared__ __nv_bfloat16 sBL[32 * B_STRIDE];
    const uint32_t uAH = smem_u32(sAH), uAL = smem_u32(sAL);
    const uint32_t uBH = smem_u32(sBH), uBL = smem_u32(sBL);

    const int b = blockIdx.z;
    const int m0 = blockIdx.y * 64;
    const int n0 = blockIdx.x * 128;
    const int tid = threadIdx.x;
    const int wid = tid >> 5, lane = tid & 31;
    const int wm = (wid & 1) * 32, wn = (wid >> 1) * 64;
    const int g = lane >> 2, tq = lane & 3;
    const int lrow = lane & 15;
    const int lcol = (lane >> 4) * 8;

    const __nv_bfloat16* AhB = Ah + (long)b * aStride;
    const __nv_bfloat16* AlB = Al + (long)b * aStride;
    const __nv_bfloat16* BhB = BSPLIT ? Bh + (long)b * bStride : nullptr;
    const __nv_bfloat16* BlB = BSPLIT ? Bl + (long)b * bStride : nullptr;
    const float* BfB = BSPLIT ? nullptr : Bf + (long)b * bStride;

    const int ar = tid >> 2, ac = (tid & 3) * 8;     // A: rows, col-octet
    const int br4 = tid >> 4, bc4 = (tid & 15) * 8;  // B split: 4 passes of 8 rows
    const int brf = tid >> 5, bcf = (tid & 31) * 4;  // B fp32: 8 passes of 4 rows

    // prefetch registers
    uint4 rA[2][2];
    uint4 rB[4][2];     // used when BSPLIT
    float4 rBF[8];      // used when !BSPLIT

    auto ldg_chunk = [&](int ch) {
        const int ko = ch * 32;
#pragma unroll
        for (int p = 0; p < 2; p++) {
            long go = (long)(m0 + ar + p * 32) * K + ko + ac;
            rA[p][0] = *(const uint4*)(AhB + go);
            rA[p][1] = *(const uint4*)(AlB + go);
        }
        if (BSPLIT) {
#pragma unroll
            for (int p = 0; p < 4; p++) {
                long go = (long)(ko + br4 + p * 8) * HW + n0 + bc4;
                rB[p][0] = *(const uint4*)(BhB + go);
                rB[p][1] = *(const uint4*)(BlB + go);
            }
        } else {
#pragma unroll
            for (int p = 0; p < 8; p++) {
                long go = (long)(ko + brf + p * 4) * HW + n0 + bcf;
                rBF[p] = *(const float4*)(BfB + go);
            }
        }
    };

    auto sts_chunk = [&]() {
#pragma unroll
        for (int p = 0; p < 2; p++) {
            int row = ar + p * 32;
            *(uint4*)(sAH + row * A_STRIDE + ac) = rA[p][0];
            *(uint4*)(sAL + row * A_STRIDE + ac) = rA[p][1];
        }
        if (BSPLIT) {
#pragma unroll
            for (int p = 0; p < 4; p++) {
                int row = br4 + p * 8;
                *(uint4*)(sBH + row * B_STRIDE + bc4) = rB[p][0];
                *(uint4*)(sBL + row * B_STRIDE + bc4) = rB[p][1];
            }
        } else {
#pragma unroll
            for (int p = 0; p < 8; p++) {
                int row = brf + p * 4;
                float4 v = rBF[p];
                __nv_bfloat16 h0, l0, h1, l1, h2, l2, h3, l3;
                split2(v.x, h0, l0); split2(v.y, h1, l1);
                split2(v.z, h2, l2); split2(v.w, h3, l3);
                uint2 hp = make_uint2(pack_bf2(h0, h1), pack_bf2(h2, h3));
                uint2 lp = make_uint2(pack_bf2(l0, l1), pack_bf2(l2, l3));
                *(uint2*)(sBH + row * B_STRIDE + bcf) = hp;
                *(uint2*)(sBL + row * B_STRIDE + bcf) = lp;
            }
        }
    };

    float c[2][8][4];
#pragma unroll
    for (int mi = 0; mi < 2; mi++)
#pragma unroll
        for (int nb = 0; nb < 8; nb++)
#pragma unroll
            for (int j = 0; j < 4; j++) c[mi][nb][j] = 0.f;

    const int NC = K / 32;
    ldg_chunk(0);
    for (int ch = 0; ch < NC; ch++) {
        sts_chunk();
        __syncthreads();
        if (ch + 1 < NC) ldg_chunk(ch + 1);   // LDG overlapped with compute below

#pragma unroll
        for (int kc = 0; kc < 2; kc++) {
            uint32_t aH[2][4], aL[2][4];
#pragma unroll
            for (int mi = 0; mi < 2; mi++) {
                uint32_t off = (uint32_t)(((wm + mi * 16 + lrow) * A_STRIDE + kc * 16 + lcol) * 2);
                ldsm4(aH[mi], uAH + off);
                ldsm4(aL[mi], uAL + off);
            }
#pragma unroll
            for (int nbp = 0; nbp < 4; nbp++) {
                uint32_t off = (uint32_t)(((kc * 16 + lrow) * B_STRIDE + wn + nbp * 16 + lcol) * 2);
                uint32_t bH[4], bL[4];
                ldsm4t(bH, uBH + off);
                ldsm4t(bL, uBL + off);
                int nb = nbp * 2;
#pragma unroll
                for (int t = 0; t < 3; t++) {
                    const uint32_t (*af)[4] = (t == 1) ? aL : aH;
                    const uint32_t* bf = (t == 2) ? bL : bH;
#pragma unroll
                    for (int mi = 0; mi < 2; mi++) {
                        hmma(c[mi][nb],     af[mi], bf[0], bf[1]);
                        hmma(c[mi][nb + 1], af[mi], bf[2], bf[3]);
                    }
                }
            }
        }
        __syncthreads();
    }

    // ---- epilogue
#pragma unroll
    for (int mi = 0; mi < 2; mi++) {
        int r0 = m0 + wm + mi * 16 + g;
        float bv0 = bias ? bias[r0] : 0.f;
        float bv1 = bias ? bias[r0 + 8] : 0.f;
#pragma unroll
        for (int nb = 0; nb < 8; nb++) {
            int col = n0 + wn + nb * 8 + tq * 2;
            float* p0 = C + (long)b * cStride + (long)r0 * HW + col;
            float* p1 = p0 + 8L * HW;
            *(float2*)p0 = make_float2(c[mi][nb][0] + bv0, c[mi][nb][1] + bv0);
            *(float2*)p1 = make_float2(c[mi][nb][2] + bv1, c[mi][nb][3] + bv1);
        }
    }
}

__global__ __launch_bounds__(128) void k1_gemm(const float* __restrict__ x,
                                               const float* __restrict__ pb) {
    mmasync_body<128, false>(g_wh, g_wl, 0L, nullptr, nullptr, x, 128L * HW,
                             g_t, 384L * HW, pb);
}
__global__ __launch_bounds__(128) void k4_gemm(float* __restrict__ out) {
    mmasync_body<256, true>(g_Ah, g_Al, 128L * 256, g_yh, g_yl, nullptr, 256L * HW,
                            out, 128L * HW, nullptr);
}

// ---------------- dual grouped conv (3x3 + 5x5 sharing input pair) ----------------
template <int MODE>
__global__ __launch_bounds__(256, 3) void dualconv_k(
    const float* __restrict__ in_ext,
    const float* __restrict__ w3, const float* __restrict__ b3,
    const float* __restrict__ w5, const float* __restrict__ b5)
{
    const int Cin = (MODE == 0) ? 384 : 128;
    const float* in = (MODE == 0) ? (const float*)g_t : in_ext;

    __shared__ float s[2 * 68 * 68];
    __shared__ float sw[68];

    const int tile = blockIdx.x;
    const int oy0 = (tile >> 1) * 64;
    const int ox0 = (tile & 1) * 64;
    const int g = blockIdx.y;
    const long bz = blockIdx.z;
    const int tid = threadIdx.x;
    const int ttx = tid & 15, tty = tid >> 4;
    const int py0 = tty * 4, px0 = ttx * 4;

    const float* in0 = in + (bz * Cin + 2 * g) * (long)HW;
    for (int idx = tid; idx < 2 * 68 * 68; idx += 256) {
        int ch = idx / 4624;
        int rem = idx - ch * 4624;
        int r = rem / 68, cc = rem - r * 68;
        int gy = oy0 - 2 + r, gx = ox0 - 2 + cc;
        float v = 0.f;
        if ((unsigned)gy < 128u && (unsigned)gx < 128u)
            v = in0[ch * HW + gy * IMG + gx];
        s[idx] = v;
    }
    if (tid < 50) sw[tid] = w5[g * 50 + tid];
    else if (tid < 68) sw[tid] = w3[g * 18 + (tid - 50)];
    __syncthreads();

    const float bias3 = b3[g], bias5 = b5[g];
    float* f3 = nullptr; long y3 = -1;
    float* f5 = nullptr; long y5 = -1;
    if (MODE == 0) {
        if (g < 128) f3 = &g_q[(bz * 128 + g) * HW];
        else         f3 = &g_k[(bz * 128 + (g - 128)) * HW];
        if (g < 64)  f5 = &g_k[(bz * 128 + 64 + g) * HW];
        else         y5 = (bz * 256 + (g - 64)) * HW;
    } else {
        y3 = (bz * 256 + 128 + g) * HW;
        y5 = (bz * 256 + 192 + g) * HW;
    }

#pragma unroll
    for (int half = 0; half < 2; half++) {
        float a3[2][4], a5[2][4];
#pragma unroll
        for (int i = 0; i < 2; i++)
#pragma unroll
            for (int j = 0; j < 4; j++) { a3[i][j] = 0.f; a5[i][j] = 0.f; }

#pragma unroll
        for (int ic = 0; ic < 2; ++ic) {
            const float* sc = s + ic * 4624 + (py0 + half * 2) * 68 + px0;
            float r[6][8];
#pragma unroll
            for (int dy = 0; dy < 6; dy++)
#pragma unroll
                for (int dx = 0; dx < 8; dx++) r[dy][dx] = sc[dy * 68 + dx];
            const float* w5s = sw + ic * 25;
#pragma unroll
            for (int t = 0; t < 25; t++) {
                float wv = w5s[t];
                int ky = t / 5, kx = t % 5;
#pragma unroll
                for (int oy = 0; oy < 2; oy++)
#pragma unroll
                    for (int ox = 0; ox < 4; ox++)
                        a5[oy][ox] += r[oy + ky][ox + kx] * wv;
            }
            const float* w3s = sw + 50 + ic * 9;
#pragma unroll
            for (int t = 0; t < 9; t++) {
                float wv = w3s[t];
                int ky = t / 3, kx = t % 3;
#pragma unroll
                for (int oy = 0; oy < 2; oy++)
#pragma unroll
                    for (int ox = 0; ox < 4; ox++)
                        a3[oy][ox] += r[oy + 1 + ky][ox + 1 + kx] * wv;
            }
        }

#pragma unroll
        for (int oy = 0; oy < 2; oy++) {
            int off = (oy0 + py0 + half * 2 + oy) * IMG + ox0 + px0;
#pragma unroll
            for (int ox = 0; ox < 4; ox++) {
                float v3 = a3[oy][ox] + bias3;
                float v5 = a5[oy][ox] + bias5;
                if (f3) f3[off + ox] = v3;
                else { __nv_bfloat16 h, l; split2(v3, h, l); g_yh[y3 + off + ox] = h; g_yl[y3 + off + ox] = l; }
                if (f5) f5[off + ox] = v5;
                else { __nv_bfloat16 h, l; split2(v5, h, l); g_yh[y5 + off + ox] = h; g_yl[y5 + off + ox] = l; }
            }
        }
    }
}

// ---------------- gram: per (b,h): G[16][16] = q @ k^T over pixels + sq norms ------
__global__ __launch_bounds__(256) void gram_k()
{
    const int bh = blockIdx.x;
    const int slice = blockIdx.y;
    const int b = bh >> 3, h = bh & 7;
    const float* qp = g_q + (long)(b * 128 + h * 16) * HW + slice * 1024;
    const float* kp = g_k + (long)(b * 128 + h * 16) * HW + slice * 1024;

    __shared__ float sq[64][17];
    __shared__ float sk[64][17];
    const int tid = threadIdx.x;
    const int phase = tid & 15, dg = (tid >> 4) & 3, eg = tid >> 6;

    float acc[4][4], aq[4], ak[4];
#pragma unroll
    for (int i = 0; i < 4; i++) {
        aq[i] = 0.f; ak[i] = 0.f;
#pragma unroll
        for (int j = 0; j < 4; j++) acc[i][j] = 0.f;
    }

    for (int blk = 0; blk < 16; ++blk) {
        for (int idx = tid; idx < 1024; idx += 256) {
            int d = idx >> 6, p = idx & 63;
            sq[p][d] = qp[(long)d * HW + blk * 64 + p];
            sk[p][d] = kp[(long)d * HW + blk * 64 + p];
        }
        __syncthreads();
        for (int p = phase; p < 64; p += 16) {
            float qv[4], kv[4];
#pragma unroll
            for (int i = 0; i < 4; i++) qv[i] = sq[p][dg * 4 + i];
#pragma unroll
            for (int j = 0; j < 4; j++) kv[j] = sk[p][eg * 4 + j];
#pragma unroll
            for (int i = 0; i < 4; i++)
#pragma unroll
                for (int j = 0; j < 4; j++) acc[i][j] += qv[i] * kv[j];
            if (eg == 0) {
#pragma unroll
                for (int i = 0; i < 4; i++) aq[i] += qv[i] * qv[i];
            }
            if (dg == 0) {
#pragma unroll
                for (int j = 0; j < 4; j++) ak[j] += kv[j] * kv[j];
            }
        }
        __syncthreads();
    }

    __shared__ float sG[288];
    for (int idx = tid; idx < 288; idx += 256) sG[idx] = 0.f;
    __syncthreads();
#pragma unroll
    for (int i = 0; i < 4; i++)
#pragma unroll
        for (int j = 0; j < 4; j++)
            atomicAdd(&sG[(dg * 4 + i) * 16 + eg * 4 + j], acc[i][j]);
    if (eg == 0) {
#pragma unroll
        for (int i = 0; i < 4; i++) atomicAdd(&sG[256 + dg * 4 + i], aq[i]);
    }
    if (dg == 0) {
#pragma unroll
        for (int j = 0; j < 4; j++) atomicAdd(&sG[272 + eg * 4 + j], ak[j]);
    }
    __syncthreads();
    float* gg = g_gram + bh * 288;
    for (int idx = tid; idx < 288; idx += 256) atomicAdd(gg + idx, sG[idx]);
}

// ---------------- attn: normalize gram, softmax, fold with proj into A (bf16 split) --
__global__ __launch_bounds__(256) void attn_k(
    const float* __restrict__ temp, const float* __restrict__ proj_w)
{
    const int b = blockIdx.x;
    const int part = blockIdx.y;
    const int tid = threadIdx.x;
    const long aBase = (long)b * 128 * 256;

    if (part == 8) {
        for (int idx = tid; idx < 128 * 128; idx += 256) {
            int c = idx >> 7, j = idx & 127;
            __nv_bfloat16 h, l;
            split2(proj_w[c * 256 + 128 + j], h, l);
            g_Ah[aBase + c * 256 + 128 + j] = h;
            g_Al[aBase + c * 256 + 128 + j] = l;
        }
        return;
    }
    const int h = part;
    const float* gg = g_gram + (b * 8 + h) * 288;
    __shared__ float sA[256], sqn[16], skn[16], srm[16], srs[16];
    if (tid < 16) {
        sqn[tid] = fmaxf(sqrtf(gg[256 + tid]), 1e-12f);
        skn[tid] = fmaxf(sqrtf(gg[272 + tid]), 1e-12f);
    }
    __syncthreads();
    const int d = tid >> 4, e = tid & 15;
    float val = gg[d * 16 + e] / (sqn[d] * skn[e]) * temp[h];
    sA[tid] = val;
    __syncthreads();
    if (e == 0) {
        float m = -1e30f;
        for (int j = 0; j < 16; j++) m = fmaxf(m, sA[d * 16 + j]);
        srm[d] = m;
    }
    __syncthreads();
    float p = expf(val - srm[d]);
    sA[tid] = p;
    __syncthreads();
    if (e == 0) {
        float ssum = 0.f;
        for (int j = 0; j < 16; j++) ssum += sA[d * 16 + j];
        srs[d] = ssum;
    }
    __syncthreads();
    sA[tid] = p / srs[d];
    __syncthreads();
    for (int o = tid; o < 2048; o += 256) {
        int c = o >> 4, ee = o & 15;
        float accv = 0.f;
#pragma unroll
        for (int dd = 0; dd < 16; dd++)
            accv += proj_w[c * 256 + h * 16 + dd] * sA[dd * 16 + ee];
        __nv_bfloat16 hh, ll;
        split2(accv, hh, ll);
        g_Ah[aBase + c * 256 + h * 16 + ee] = hh;
        g_Al[aBase + c * 256 + h * 16 + ee] = ll;
    }
}

// ---------------- launch ----------------
extern "C" void kernel_launch(void* const* d_in, const int* in_sizes, int n_in,
                              void* d_out, int out_size)
{
    const float* x      = (const float*)d_in[0];
    const float* pos_w  = (const float*)d_in[1];
    const float* pos_b  = (const float*)d_in[2];
    const float* qd3_w  = (const float*)d_in[3];
    const float* qd3_b  = (const float*)d_in[4];
    const float* qd5_w  = (const float*)d_in[5];
    const float* qd5_b  = (const float*)d_in[6];
    const float* temp   = (const float*)d_in[7];
    const float* d3_w   = (const float*)d_in[8];
    const float* d3_b   = (const float*)d_in[9];
    const float* d5_w   = (const float*)d_in[10];
    const float* d5_b   = (const float*)d_in[11];
    const float* proj_w = (const float*)d_in[12];
    float* out = (float*)d_out;

    zero_gram_k<<<72, 256>>>();
    convert_w_k<<<48, 256>>>(pos_w);
    k1_gemm<<<dim3(128, 6, 8), 128>>>(x, pos_b);
    dualconv_k<0><<<dim3(4, 192, 8), 256>>>(nullptr, qd3_w, qd3_b, qd5_w, qd5_b);
    dualconv_k<1><<<dim3(4, 64, 8), 256>>>(x, d3_w, d3_b, d5_w, d5_b);
    gram_k<<<dim3(64, 16), 256>>>();
    attn_k<<<dim3(8, 9), 256>>>(temp, proj_w);
    k4_gemm<<<dim3(128, 2, 8), 128>>>(out);
}

// round 12
// speedup vs baseline: 1.5426x; 1.0155x over previous
#include <cuda_runtime.h>
#include <cuda_bf16.h>
#include <cstdint>

#define HW 16384
#define IMG 128

// ---------------- scratch (static __device__, no allocs) ----------------
__device__ float g_t[8L * 384 * HW];            // pos-conv output (B,384,H,W) fp32
__device__ float g_q[8L * 128 * HW];            // q channels fp32
__device__ float g_k[8L * 128 * HW];            // k channels fp32
__device__ __nv_bfloat16 g_yh[8L * 256 * HW];   // [v|d3|d5] split hi
__device__ __nv_bfloat16 g_yl[8L * 256 * HW];   // [v|d3|d5] split lo
__device__ __nv_bfloat16 g_wh[384 * 128];       // pos_w split hi
__device__ __nv_bfloat16 g_wl[384 * 128];       // pos_w split lo
__device__ __nv_bfloat16 g_Ah[8 * 128 * 256];   // folded proj*attn split hi
__device__ __nv_bfloat16 g_Al[8 * 128 * 256];   // folded proj*attn split lo
__device__ float g_gram[64 * 288];              // per (b,h): G[256], qn[16], kn[16]

__device__ __forceinline__ void split2(float v, __nv_bfloat16& h, __nv_bfloat16& l) {
    h = __float2bfloat16(v);
    l = __float2bfloat16(v - __bfloat162float(h));
}
__device__ __forceinline__ uint32_t smem_u32(const void* p) {
    uint32_t a;
    asm("{ .reg .u64 t; cvta.to.shared.u64 t, %1; cvt.u32.u64 %0, t; }" : "=r"(a) : "l"(p));
    return a;
}
__device__ __forceinline__ uint32_t pack_bf2(__nv_bfloat16 a, __nv_bfloat16 b) {
    return (uint32_t)__bfloat16_as_ushort(a) | ((uint32_t)__bfloat16_as_ushort(b) << 16);
}

// ---------------- zero gram accumulators ----------------
__global__ void zero_gram_k() {
    int i = blockIdx.x * 256 + threadIdx.x;
    if (i < 64 * 288) g_gram[i] = 0.f;
}

// ---------------- split conversion for pos_w ----------------
__global__ void convert_w_k(const float* __restrict__ w) {
    long i = ((long)blockIdx.x * 256 + threadIdx.x) * 4;
    float4 v = *(const float4*)(w + i);
    __nv_bfloat16 h, l;
    split2(v.x, h, l); g_wh[i + 0] = h; g_wl[i + 0] = l;
    split2(v.y, h, l); g_wh[i + 1] = h; g_wl[i + 1] = l;
    split2(v.z, h, l); g_wh[i + 2] = h; g_wl[i + 2] = l;
    split2(v.w, h, l); g_wh[i + 3] = h; g_wl[i + 3] = l;
}

// ---------------- mma.sync helpers ----------------
__device__ __forceinline__ void hmma(float* c, const uint32_t* a, uint32_t b0, uint32_t b1) {
    asm volatile(
        "mma.sync.aligned.m16n8k16.row.col.f32.bf16.bf16.f32 "
        "{%0,%1,%2,%3}, {%4,%5,%6,%7}, {%8,%9}, {%0,%1,%2,%3};"
        : "+f"(c[0]), "+f"(c[1]), "+f"(c[2]), "+f"(c[3])
        : "r"(a[0]), "r"(a[1]), "r"(a[2]), "r"(a[3]), "r"(b0), "r"(b1));
}
__device__ __forceinline__ void ldsm4(uint32_t* r, uint32_t addr) {
    asm volatile("ldmatrix.sync.aligned.m8n8.x4.shared.b16 {%0,%1,%2,%3}, [%4];"
        : "=r"(r[0]), "=r"(r[1]), "=r"(r[2]), "=r"(r[3]) : "r"(addr));
}
__device__ __forceinline__ void ldsm4t(uint32_t* r, uint32_t addr) {
    asm volatile("ldmatrix.sync.aligned.m8n8.x4.trans.shared.b16 {%0,%1,%2,%3}, [%4];"
        : "=r"(r[0]), "=r"(r[1]), "=r"(r[2]), "=r"(r[3]) : "r"(addr));
}

// ---------------- bf16-split GEMM, register double-buffered ----------------
#define A_STRIDE 40
#define B_STRIDE 136

template <int K, bool BSPLIT>
__device__ __forceinline__ void mmasync_body(
    const __nv_bfloat16* __restrict__ Ah, const __nv_bfloat16* __restrict__ Al,
    long aStride,
    const __nv_bfloat16* __restrict__ Bh, const __nv_bfloat16* __restrict__ Bl,
    const float* __restrict__ Bf, long bStride,
    float* __restrict__ C, long cStride, const float* __restrict__ bias)
{
    __shared__ __nv_bfloat16 sAH[64 * A_STRIDE];
    __shared__ __nv_bfloat16 sAL[64 * A_STRIDE];
    __shared__ __nv_bfloat16 sBH[32 * B_STRIDE];
    __shared__ __nv_bfloat16 sBL[32 * B_STRIDE];
    const uint32_t uAH = smem_u32(sAH), uAL = smem_u32(sAL);
    const uint32_t uBH = smem_u32(sBH), uBL = smem_u32(sBL);

    const int b = blockIdx.z;
    const int m0 = blockIdx.y * 64;
    const int n0 = blockIdx.x * 128;
    const int tid = threadIdx.x;
    const int wid = tid >> 5, lane = tid & 31;
    const int wm = (wid & 1) * 32, wn = (wid >> 1) * 64;
    const int g = lane >> 2, tq = lane & 3;
    const int lrow = lane & 15;
    const int lcol = (lane >> 4) * 8;

    const __nv_bfloat16* AhB = Ah + (long)b * aStride;
    const __nv_bfloat16* AlB = Al + (long)b * aStride;
    const __nv_bfloat16* BhB = BSPLIT ? Bh + (long)b * bStride : nullptr;
    const __nv_bfloat16* BlB = BSPLIT ? Bl + (long)b * bStride : nullptr;
    const float* BfB = BSPLIT ? nullptr : Bf + (long)b * bStride;

    const int ar = tid >> 2, ac = (tid & 3) * 8;
    const int br4 = tid >> 4, bc4 = (tid & 15) * 8;
    const int brf = tid >> 5, bcf = (tid & 31) * 4;

    uint4 rA[2][2];
    uint4 rB[4][2];
    float4 rBF[8];

    auto ldg_chunk = [&](int ch) {
        const int ko = ch * 32;
#pragma unroll
        for (int p = 0; p < 2; p++) {
            long go = (long)(m0 + ar + p * 32) * K + ko + ac;
            rA[p][0] = *(const uint4*)(AhB + go);
            rA[p][1] = *(const uint4*)(AlB + go);
        }
        if (BSPLIT) {
#pragma unroll
            for (int p = 0; p < 4; p++) {
                long go = (long)(ko + br4 + p * 8) * HW + n0 + bc4;
                rB[p][0] = *(const uint4*)(BhB + go);
                rB[p][1] = *(const uint4*)(BlB + go);
            }
        } else {
#pragma unroll
            for (int p = 0; p < 8; p++) {
                long go = (long)(ko + brf + p * 4) * HW + n0 + bcf;
                rBF[p] = *(const float4*)(BfB + go);
            }
        }
    };

    auto sts_chunk = [&]() {
#pragma unroll
        for (int p = 0; p < 2; p++) {
            int row = ar + p * 32;
            *(uint4*)(sAH + row * A_STRIDE + ac) = rA[p][0];
            *(uint4*)(sAL + row * A_STRIDE + ac) = rA[p][1];
        }
        if (BSPLIT) {
#pragma unroll
            for (int p = 0; p < 4; p++) {
                int row = br4 + p * 8;
                *(uint4*)(sBH + row * B_STRIDE + bc4) = rB[p][0];
                *(uint4*)(sBL + row * B_STRIDE + bc4) = rB[p][1];
            }
        } else {
#pragma unroll
            for (int p = 0; p < 8; p++) {
                int row = brf + p * 4;
                float4 v = rBF[p];
                __nv_bfloat16 h0, l0, h1, l1, h2, l2, h3, l3;
                split2(v.x, h0, l0); split2(v.y, h1, l1);
                split2(v.z, h2, l2); split2(v.w, h3, l3);
                uint2 hp = make_uint2(pack_bf2(h0, h1), pack_bf2(h2, h3));
                uint2 lp = make_uint2(pack_bf2(l0, l1), pack_bf2(l2, l3));
                *(uint2*)(sBH + row * B_STRIDE + bcf) = hp;
                *(uint2*)(sBL + row * B_STRIDE + bcf) = lp;
            }
        }
    };

    float c[2][8][4];
#pragma unroll
    for (int mi = 0; mi < 2; mi++)
#pragma unroll
        for (int nb = 0; nb < 8; nb++)
#pragma unroll
            for (int j = 0; j < 4; j++) c[mi][nb][j] = 0.f;

    const int NC = K / 32;
    ldg_chunk(0);
    for (int ch = 0; ch < NC; ch++) {
        sts_chunk();
        __syncthreads();
        if (ch + 1 < NC) ldg_chunk(ch + 1);

#pragma unroll
        for (int kc = 0; kc < 2; kc++) {
            uint32_t aH[2][4], aL[2][4];
#pragma unroll
            for (int mi = 0; mi < 2; mi++) {
                uint32_t off = (uint32_t)(((wm + mi * 16 + lrow) * A_STRIDE + kc * 16 + lcol) * 2);
                ldsm4(aH[mi], uAH + off);
                ldsm4(aL[mi], uAL + off);
            }
#pragma unroll
            for (int nbp = 0; nbp < 4; nbp++) {
                uint32_t off = (uint32_t)(((kc * 16 + lrow) * B_STRIDE + wn + nbp * 16 + lcol) * 2);
                uint32_t bH[4], bL[4];
                ldsm4t(bH, uBH + off);
                ldsm4t(bL, uBL + off);
                int nb = nbp * 2;
#pragma unroll
                for (int t = 0; t < 3; t++) {
                    const uint32_t (*af)[4] = (t == 1) ? aL : aH;
                    const uint32_t* bf = (t == 2) ? bL : bH;
#pragma unroll
                    for (int mi = 0; mi < 2; mi++) {
                        hmma(c[mi][nb],     af[mi], bf[0], bf[1]);
                        hmma(c[mi][nb + 1], af[mi], bf[2], bf[3]);
                    }
                }
            }
        }
        __syncthreads();
    }

#pragma unroll
    for (int mi = 0; mi < 2; mi++) {
        int r0 = m0 + wm + mi * 16 + g;
        float bv0 = bias ? bias[r0] : 0.f;
        float bv1 = bias ? bias[r0 + 8] : 0.f;
#pragma unroll
        for (int nb = 0; nb < 8; nb++) {
            int col = n0 + wn + nb * 8 + tq * 2;
            float* p0 = C + (long)b * cStride + (long)r0 * HW + col;
            float* p1 = p0 + 8L * HW;
            *(float2*)p0 = make_float2(c[mi][nb][0] + bv0, c[mi][nb][1] + bv0);
            *(float2*)p1 = make_float2(c[mi][nb][2] + bv1, c[mi][nb][3] + bv1);
        }
    }
}

__global__ __launch_bounds__(128) void k1_gemm(const float* __restrict__ x,
                                               const float* __restrict__ pb) {
    mmasync_body<128, false>(g_wh, g_wl, 0L, nullptr, nullptr, x, 128L * HW,
                             g_t, 384L * HW, pb);
}
__global__ __launch_bounds__(128) void k4_gemm(float* __restrict__ out) {
    mmasync_body<256, true>(g_Ah, g_Al, 128L * 256, g_yh, g_yl, nullptr, 256L * HW,
                            out, 128L * HW, nullptr);
}

// ---------------- dual grouped conv (3x3 + 5x5 sharing input pair) ----------------
// Halo tile: 68 rows x 72 cols per channel (float4-aligned, division-free load).
// Smem col j holds gx = ox0 - 4 + j; every float4 chunk is fully in/out of image.
#define CONV_ROW 72
#define CONV_CH (68 * CONV_ROW)

template <int MODE>
__global__ __launch_bounds__(256, 3) void dualconv_k(
    const float* __restrict__ in_ext,
    const float* __restrict__ w3, const float* __restrict__ b3,
    const float* __restrict__ w5, const float* __restrict__ b5)
{
    const int Cin = (MODE == 0) ? 384 : 128;
    const float* in = (MODE == 0) ? (const float*)g_t : in_ext;

    __shared__ float s[2 * CONV_CH];
    __shared__ float sw[68];

    const int tile = blockIdx.x;
    const int oy0 = (tile >> 1) * 64;
    const int ox0 = (tile & 1) * 64;
    const int g = blockIdx.y;
    const long bz = blockIdx.z;
    const int tid = threadIdx.x;
    const int ttx = tid & 15, tty = tid >> 4;
    const int py0 = tty * 4, px0 = ttx * 4;

    const float* in0 = in + (bz * Cin + 2 * g) * (long)HW;

    // ---- vectorized halo load: rows 0..67 (gy = oy0-2+row), cols 0..71 (gx = ox0-4+col)
    {
        const int lr = tid >> 4;     // 0..15: row within pass
        const int lc = tid & 15;     // chunk 0..15 (plus 16/17 for lc<2)
#pragma unroll
        for (int ch = 0; ch < 2; ch++) {
            const float* inc = in0 + ch * HW;
            float* sch = s + ch * CONV_CH;
#pragma unroll
            for (int rp = 0; rp < 80; rp += 16) {
                int r = rp + lr;
                if (r < 68) {
                    int gy = oy0 - 2 + r;
                    bool rowok = (unsigned)gy < 128u;
                    const float* rowp = inc + gy * IMG;
                    {
                        int gx0 = ox0 - 4 + lc * 4;
                        float4 v = make_float4(0.f, 0.f, 0.f, 0.f);
                        if (rowok && (unsigned)gx0 < 125u) v = *(const float4*)(rowp + gx0);
                        *(float4*)(sch + r * CONV_ROW + lc * 4) = v;
                    }
                    if (lc < 2) {
                        int j = 16 + lc;
                        int gx0 = ox0 - 4 + j * 4;
                        float4 v = make_float4(0.f, 0.f, 0.f, 0.f);
                        if (rowok && (unsigned)gx0 < 125u) v = *(const float4*)(rowp + gx0);
                        *(float4*)(sch + r * CONV_ROW + j * 4) = v;
                    }
                }
            }
        }
    }
    if (tid < 50) sw[tid] = w5[g * 50 + tid];
    else if (tid < 68) sw[tid] = w3[g * 18 + (tid - 50)];
    __syncthreads();

    const float bias3 = b3[g], bias5 = b5[g];
    float* f3 = nullptr; long y3 = -1;
    float* f5 = nullptr; long y5 = -1;
    if (MODE == 0) {
        if (g < 128) f3 = &g_q[(bz * 128 + g) * HW];
        else         f3 = &g_k[(bz * 128 + (g - 128)) * HW];
        if (g < 64)  f5 = &g_k[(bz * 128 + 64 + g) * HW];
        else         y5 = (bz * 256 + (g - 64)) * HW;
    } else {
        y3 = (bz * 256 + 128 + g) * HW;
        y5 = (bz * 256 + 192 + g) * HW;
    }

#pragma unroll
    for (int half = 0; half < 2; half++) {
        float a3[2][4], a5[2][4];
#pragma unroll
        for (int i = 0; i < 2; i++)
#pragma unroll
            for (int j = 0; j < 4; j++) { a3[i][j] = 0.f; a5[i][j] = 0.f; }

#pragma unroll
        for (int ic = 0; ic < 2; ++ic) {
            // smem window: rows py0+half*2 .., cols px0+2 .. (gx alignment shift)
            const float* sc = s + ic * CONV_CH + (py0 + half * 2) * CONV_ROW + px0 + 2;
            float r[6][8];
#pragma unroll
            for (int dy = 0; dy < 6; dy++)
#pragma unroll
                for (int dx = 0; dx < 8; dx++) r[dy][dx] = sc[dy * CONV_ROW + dx];
            const float* w5s = sw + ic * 25;
#pragma unroll
            for (int t = 0; t < 25; t++) {
                float wv = w5s[t];
                int ky = t / 5, kx = t % 5;
#pragma unroll
                for (int oy = 0; oy < 2; oy++)
#pragma unroll
                    for (int ox = 0; ox < 4; ox++)
                        a5[oy][ox] += r[oy + ky][ox + kx] * wv;
            }
            const float* w3s = sw + 50 + ic * 9;
#pragma unroll
            for (int t = 0; t < 9; t++) {
                float wv = w3s[t];
                int ky = t / 3, kx = t % 3;
#pragma unroll
                for (int oy = 0; oy < 2; oy++)
#pragma unroll
                    for (int ox = 0; ox < 4; ox++)
                        a3[oy][ox] += r[oy + 1 + ky][ox + 1 + kx] * wv;
            }
        }

#pragma unroll
        for (int oy = 0; oy < 2; oy++) {
            int off = (oy0 + py0 + half * 2 + oy) * IMG + ox0 + px0;
#pragma unroll
            for (int ox = 0; ox < 4; ox++) {
                float v3 = a3[oy][ox] + bias3;
                float v5 = a5[oy][ox] + bias5;
                if (f3) f3[off + ox] = v3;
                else { __nv_bfloat16 h, l; split2(v3, h, l); g_yh[y3 + off + ox] = h; g_yl[y3 + off + ox] = l; }
                if (f5) f5[off + ox] = v5;
                else { __nv_bfloat16 h, l; split2(v5, h, l); g_yh[y5 + off + ox] = h; g_yl[y5 + off + ox] = l; }
            }
        }
    }
}

// ---------------- gram: per (b,h): G[16][16] = q @ k^T over pixels + sq norms ------
__global__ __launch_bounds__(256) void gram_k()
{
    const int bh = blockIdx.x;
    const int slice = blockIdx.y;
    const int b = bh >> 3, h = bh & 7;
    const float* qp = g_q + (long)(b * 128 + h * 16) * HW + slice * 1024;
    const float* kp = g_k + (long)(b * 128 + h * 16) * HW + slice * 1024;

    __shared__ float sq[64][17];
    __shared__ float sk[64][17];
    const int tid = threadIdx.x;
    const int phase = tid & 15, dg = (tid >> 4) & 3, eg = tid >> 6;

    float acc[4][4], aq[4], ak[4];
#pragma unroll
    for (int i = 0; i < 4; i++) {
        aq[i] = 0.f; ak[i] = 0.f;
#pragma unroll
        for (int j = 0; j < 4; j++) acc[i][j] = 0.f;
    }

    for (int blk = 0; blk < 16; ++blk) {
        for (int idx = tid; idx < 1024; idx += 256) {
            int d = idx >> 6, p = idx & 63;
            sq[p][d] = qp[(long)d * HW + blk * 64 + p];
            sk[p][d] = kp[(long)d * HW + blk * 64 + p];
        }
        __syncthreads();
        for (int p = phase; p < 64; p += 16) {
            float qv[4], kv[4];
#pragma unroll
            for (int i = 0; i < 4; i++) qv[i] = sq[p][dg * 4 + i];
#pragma unroll
            for (int j = 0; j < 4; j++) kv[j] = sk[p][eg * 4 + j];
#pragma unroll
            for (int i = 0; i < 4; i++)
#pragma unroll
                for (int j = 0; j < 4; j++) acc[i][j] += qv[i] * kv[j];
            if (eg == 0) {
#pragma unroll
                for (int i = 0; i < 4; i++) aq[i] += qv[i] * qv[i];
            }
            if (dg == 0) {
#pragma unroll
                for (int j = 0; j < 4; j++) ak[j] += kv[j] * kv[j];
            }
        }
        __syncthreads();
    }

    __shared__ float sG[288];
    for (int idx = tid; idx < 288; idx += 256) sG[idx] = 0.f;
    __syncthreads();
#pragma unroll
    for (int i = 0; i < 4; i++)
#pragma unroll
        for (int j = 0; j < 4; j++)
            atomicAdd(&sG[(dg * 4 + i) * 16 + eg * 4 + j], acc[i][j]);
    if (eg == 0) {
#pragma unroll
        for (int i = 0; i < 4; i++) atomicAdd(&sG[256 + dg * 4 + i], aq[i]);
    }
    if (dg == 0) {
#pragma unroll
        for (int j = 0; j < 4; j++) atomicAdd(&sG[272 + eg * 4 + j], ak[j]);
    }
    __syncthreads();
    float* gg = g_gram + bh * 288;
    for (int idx = tid; idx < 288; idx += 256) atomicAdd(gg + idx, sG[idx]);
}

// ---------------- attn: normalize gram, softmax, fold with proj into A (bf16 split) --
__global__ __launch_bounds__(256) void attn_k(
    const float* __restrict__ temp, const float* __restrict__ proj_w)
{
    const int b = blockIdx.x;
    const int part = blockIdx.y;
    const int tid = threadIdx.x;
    const long aBase = (long)b * 128 * 256;

    if (part == 8) {
        for (int idx = tid; idx < 128 * 128; idx += 256) {
            int c = idx >> 7, j = idx & 127;
            __nv_bfloat16 h, l;
            split2(proj_w[c * 256 + 128 + j], h, l);
            g_Ah[aBase + c * 256 + 128 + j] = h;
            g_Al[aBase + c * 256 + 128 + j] = l;
        }
        return;
    }
    const int h = part;
    const float* gg = g_gram + (b * 8 + h) * 288;
    __shared__ float sA[256], sqn[16], skn[16], srm[16], srs[16];
    if (tid < 16) {
        sqn[tid] = fmaxf(sqrtf(gg[256 + tid]), 1e-12f);
        skn[tid] = fmaxf(sqrtf(gg[272 + tid]), 1e-12f);
    }
    __syncthreads();
    const int d = tid >> 4, e = tid & 15;
    float val = gg[d * 16 + e] / (sqn[d] * skn[e]) * temp[h];
    sA[tid] = val;
    __syncthreads();
    if (e == 0) {
        float m = -1e30f;
        for (int j = 0; j < 16; j++) m = fmaxf(m, sA[d * 16 + j]);
        srm[d] = m;
    }
    __syncthreads();
    float p = expf(val - srm[d]);
    sA[tid] = p;
    __syncthreads();
    if (e == 0) {
        float ssum = 0.f;
        for (int j = 0; j < 16; j++) ssum += sA[d * 16 + j];
        srs[d] = ssum;
    }
    __syncthreads();
    sA[tid] = p / srs[d];
    __syncthreads();
    for (int o = tid; o < 2048; o += 256) {
        int c = o >> 4, ee = o & 15;
        float accv = 0.f;
#pragma unroll
        for (int dd = 0; dd < 16; dd++)
            accv += proj_w[c * 256 + h * 16 + dd] * sA[dd * 16 + ee];
        __nv_bfloat16 hh, ll;
        split2(accv, hh, ll);
        g_Ah[aBase + c * 256 + h * 16 + ee] = hh;
        g_Al[aBase + c * 256 + h * 16 + ee] = ll;
    }
}

// ---------------- launch ----------------
extern "C" void kernel_launch(void* const* d_in, const int* in_sizes, int n_in,
                              void* d_out, int out_size)
{
    const float* x      = (const float*)d_in[0];
    const float* pos_w  = (const float*)d_in[1];
    const float* pos_b  = (const float*)d_in[2];
    const float* qd3_w  = (const float*)d_in[3];
    const float* qd3_b  = (const float*)d_in[4];
    const float* qd5_w  = (const float*)d_in[5];
    const float* qd5_b  = (const float*)d_in[6];
    const float* temp   = (const float*)d_in[7];
    const float* d3_w   = (const float*)d_in[8];
    const float* d3_b   = (const float*)d_in[9];
    const float* d5_w   = (const float*)d_in[10];
    const float* d5_b   = (const float*)d_in[11];
    const float* proj_w = (const float*)d_in[12];
    float* out = (float*)d_out;

    zero_gram_k<<<72, 256>>>();
    convert_w_k<<<48, 256>>>(pos_w);
    k1_gemm<<<dim3(128, 6, 8), 128>>>(x, pos_b);
    dualconv_k<0><<<dim3(4, 192, 8), 256>>>(nullptr, qd3_w, qd3_b, qd5_w, qd5_b);
    dualconv_k<1><<<dim3(4, 64, 8), 256>>>(x, d3_w, d3_b, d5_w, d5_b);
    gram_k<<<dim3(64, 16), 256>>>();
    attn_k<<<dim3(8, 9), 256>>>(temp, proj_w);
    k4_gemm<<<dim3(128, 2, 8), 128>>>(out);
}

// round 13
// speedup vs baseline: 1.6086x; 1.0428x over previous
#include <cuda_runtime.h>
#include <cuda_bf16.h>
#include <cstdint>

#define HW 16384
#define IMG 128

// ---------------- scratch (static __device__, no allocs) ----------------
__device__ float g_t[8L * 384 * HW];            // pos-conv output (B,384,H,W) fp32
__device__ float g_q[8L * 128 * HW];            // q channels fp32
__device__ float g_k[8L * 128 * HW];            // k channels fp32
__device__ __nv_bfloat16 g_yh[8L * 256 * HW];   // [v|d3|d5] split hi
__device__ __nv_bfloat16 g_yl[8L * 256 * HW];   // [v|d3|d5] split lo
__device__ __nv_bfloat16 g_wh[384 * 128];       // pos_w split hi
__device__ __nv_bfloat16 g_wl[384 * 128];       // pos_w split lo
__device__ __nv_bfloat16 g_Ah[8 * 128 * 256];   // folded proj*attn split hi
__device__ __nv_bfloat16 g_Al[8 * 128 * 256];   // folded proj*attn split lo
__device__ float g_gram[64 * 288];              // per (b,h): G[256], qn[16], kn[16]

__device__ __forceinline__ void split2(float v, __nv_bfloat16& h, __nv_bfloat16& l) {
    h = __float2bfloat16(v);
    l = __float2bfloat16(v - __bfloat162float(h));
}
__device__ __forceinline__ uint32_t smem_u32(const void* p) {
    uint32_t a;
    asm("{ .reg .u64 t; cvta.to.shared.u64 t, %1; cvt.u32.u64 %0, t; }" : "=r"(a) : "l"(p));
    return a;
}
__device__ __forceinline__ uint32_t pack_bf2(__nv_bfloat16 a, __nv_bfloat16 b) {
    return (uint32_t)__bfloat16_as_ushort(a) | ((uint32_t)__bfloat16_as_ushort(b) << 16);
}

// ---------------- zero gram accumulators ----------------
__global__ void zero_gram_k() {
    int i = blockIdx.x * 256 + threadIdx.x;
    if (i < 64 * 288) g_gram[i] = 0.f;
}

// ---------------- split conversion for pos_w ----------------
__global__ void convert_w_k(const float* __restrict__ w) {
    long i = ((long)blockIdx.x * 256 + threadIdx.x) * 4;
    float4 v = *(const float4*)(w + i);
    __nv_bfloat16 h, l;
    split2(v.x, h, l); g_wh[i + 0] = h; g_wl[i + 0] = l;
    split2(v.y, h, l); g_wh[i + 1] = h; g_wl[i + 1] = l;
    split2(v.z, h, l); g_wh[i + 2] = h; g_wl[i + 2] = l;
    split2(v.w, h, l); g_wh[i + 3] = h; g_wl[i + 3] = l;
}

// ---------------- mma.sync helpers ----------------
__device__ __forceinline__ void hmma(float* c, const uint32_t* a, uint32_t b0, uint32_t b1) {
    asm volatile(
        "mma.sync.aligned.m16n8k16.row.col.f32.bf16.bf16.f32 "
        "{%0,%1,%2,%3}, {%4,%5,%6,%7}, {%8,%9}, {%0,%1,%2,%3};"
        : "+f"(c[0]), "+f"(c[1]), "+f"(c[2]), "+f"(c[3])
        : "r"(a[0]), "r"(a[1]), "r"(a[2]), "r"(a[3]), "r"(b0), "r"(b1));
}
__device__ __forceinline__ void ldsm4(uint32_t* r, uint32_t addr) {
    asm volatile("ldmatrix.sync.aligned.m8n8.x4.shared.b16 {%0,%1,%2,%3}, [%4];"
        : "=r"(r[0]), "=r"(r[1]), "=r"(r[2]), "=r"(r[3]) : "r"(addr));
}
__device__ __forceinline__ void ldsm4t(uint32_t* r, uint32_t addr) {
    asm volatile("ldmatrix.sync.aligned.m8n8.x4.trans.shared.b16 {%0,%1,%2,%3}, [%4];"
        : "=r"(r[0]), "=r"(r[1]), "=r"(r[2]), "=r"(r[3]) : "r"(addr));
}

// ---------------- bf16-split GEMM, register double-buffered ----------------
#define A_STRIDE 40
#define B_STRIDE 136

template <int K, bool BSPLIT>
__device__ __forceinline__ void mmasync_body(
    const __nv_bfloat16* __restrict__ Ah, const __nv_bfloat16* __restrict__ Al,
    long aStride,
    const __nv_bfloat16* __restrict__ Bh, const __nv_bfloat16* __restrict__ Bl,
    const float* __restrict__ Bf, long bStride,
    float* __restrict__ C, long cStride, const float* __restrict__ bias)
{
    __shared__ __nv_bfloat16 sAH[64 * A_STRIDE];
    __shared__ __nv_bfloat16 sAL[64 * A_STRIDE];
    __shared__ __nv_bfloat16 sBH[32 * B_STRIDE];
    __shared__ __nv_bfloat16 sBL[32 * B_STRIDE];
    const uint32_t uAH = smem_u32(sAH), uAL = smem_u32(sAL);
    const uint32_t uBH = smem_u32(sBH), uBL = smem_u32(sBL);

    const int b = blockIdx.z;
    const int m0 = blockIdx.y * 64;
    const int n0 = blockIdx.x * 128;
    const int tid = threadIdx.x;
    const int wid = tid >> 5, lane = tid & 31;
    const int wm = (wid & 1) * 32, wn = (wid >> 1) * 64;
    const int g = lane >> 2, tq = lane & 3;
    const int lrow = lane & 15;
    const int lcol = (lane >> 4) * 8;

    const __nv_bfloat16* AhB = Ah + (long)b * aStride;
    const __nv_bfloat16* AlB = Al + (long)b * aStride;
    const __nv_bfloat16* BhB = BSPLIT ? Bh + (long)b * bStride : nullptr;
    const __nv_bfloat16* BlB = BSPLIT ? Bl + (long)b * bStride : nullptr;
    const float* BfB = BSPLIT ? nullptr : Bf + (long)b * bStride;

    const int ar = tid >> 2, ac = (tid & 3) * 8;
    const int br4 = tid >> 4, bc4 = (tid & 15) * 8;
    const int brf = tid >> 5, bcf = (tid & 31) * 4;

    uint4 rA[2][2];
    uint4 rB[4][2];
    float4 rBF[8];

    auto ldg_chunk = [&](int ch) {
        const int ko = ch * 32;
#pragma unroll
        for (int p = 0; p < 2; p++) {
            long go = (long)(m0 + ar + p * 32) * K + ko + ac;
            rA[p][0] = *(const uint4*)(AhB + go);
            rA[p][1] = *(const uint4*)(AlB + go);
        }
        if (BSPLIT) {
#pragma unroll
            for (int p = 0; p < 4; p++) {
                long go = (long)(ko + br4 + p * 8) * HW + n0 + bc4;
                rB[p][0] = *(const uint4*)(BhB + go);
                rB[p][1] = *(const uint4*)(BlB + go);
            }
        } else {
#pragma unroll
            for (int p = 0; p < 8; p++) {
                long go = (long)(ko + brf + p * 4) * HW + n0 + bcf;
                rBF[p] = *(const float4*)(BfB + go);
            }
        }
    };

    auto sts_chunk = [&]() {
#pragma unroll
        for (int p = 0; p < 2; p++) {
            int row = ar + p * 32;
            *(uint4*)(sAH + row * A_STRIDE + ac) = rA[p][0];
            *(uint4*)(sAL + row * A_STRIDE + ac) = rA[p][1];
        }
        if (BSPLIT) {
#pragma unroll
            for (int p = 0; p < 4; p++) {
                int row = br4 + p * 8;
                *(uint4*)(sBH + row * B_STRIDE + bc4) = rB[p][0];
                *(uint4*)(sBL + row * B_STRIDE + bc4) = rB[p][1];
            }
        } else {
#pragma unroll
            for (int p = 0; p < 8; p++) {
                int row = brf + p * 4;
                float4 v = rBF[p];
                __nv_bfloat16 h0, l0, h1, l1, h2, l2, h3, l3;
                split2(v.x, h0, l0); split2(v.y, h1, l1);
                split2(v.z, h2, l2); split2(v.w, h3, l3);
                uint2 hp = make_uint2(pack_bf2(h0, h1), pack_bf2(h2, h3));
                uint2 lp = make_uint2(pack_bf2(l0, l1), pack_bf2(l2, l3));
                *(uint2*)(sBH + row * B_STRIDE + bcf) = hp;
                *(uint2*)(sBL + row * B_STRIDE + bcf) = lp;
            }
        }
    };

    float c[2][8][4];
#pragma unroll
    for (int mi = 0; mi < 2; mi++)
#pragma unroll
        for (int nb = 0; nb < 8; nb++)
#pragma unroll
            for (int j = 0; j < 4; j++) c[mi][nb][j] = 0.f;

    const int NC = K / 32;
    ldg_chunk(0);
    for (int ch = 0; ch < NC; ch++) {
        sts_chunk();
        __syncthreads();
        if (ch + 1 < NC) ldg_chunk(ch + 1);

#pragma unroll
        for (int kc = 0; kc < 2; kc++) {
            uint32_t aH[2][4], aL[2][4];
#pragma unroll
            for (int mi = 0; mi < 2; mi++) {
                uint32_t off = (uint32_t)(((wm + mi * 16 + lrow) * A_STRIDE + kc * 16 + lcol) * 2);
                ldsm4(aH[mi], uAH + off);
                ldsm4(aL[mi], uAL + off);
            }
#pragma unroll
            for (int nbp = 0; nbp < 4; nbp++) {
                uint32_t off = (uint32_t)(((kc * 16 + lrow) * B_STRIDE + wn + nbp * 16 + lcol) * 2);
                uint32_t bH[4], bL[4];
                ldsm4t(bH, uBH + off);
                ldsm4t(bL, uBL + off);
                int nb = nbp * 2;
#pragma unroll
                for (int t = 0; t < 3; t++) {
                    const uint32_t (*af)[4] = (t == 1) ? aL : aH;
                    const uint32_t* bf = (t == 2) ? bL : bH;
#pragma unroll
                    for (int mi = 0; mi < 2; mi++) {
                        hmma(c[mi][nb],     af[mi], bf[0], bf[1]);
                        hmma(c[mi][nb + 1], af[mi], bf[2], bf[3]);
                    }
                }
            }
        }
        __syncthreads();
    }

#pragma unroll
    for (int mi = 0; mi < 2; mi++) {
        int r0 = m0 + wm + mi * 16 + g;
        float bv0 = bias ? bias[r0] : 0.f;
        float bv1 = bias ? bias[r0 + 8] : 0.f;
#pragma unroll
        for (int nb = 0; nb < 8; nb++) {
            int col = n0 + wn + nb * 8 + tq * 2;
            float* p0 = C + (long)b * cStride + (long)r0 * HW + col;
            float* p1 = p0 + 8L * HW;
            *(float2*)p0 = make_float2(c[mi][nb][0] + bv0, c[mi][nb][1] + bv0);
            *(float2*)p1 = make_float2(c[mi][nb][2] + bv1, c[mi][nb][3] + bv1);
        }
    }
}

__global__ __launch_bounds__(128) void k1_gemm(const float* __restrict__ x,
                                               const float* __restrict__ pb) {
    mmasync_body<128, false>(g_wh, g_wl, 0L, nullptr, nullptr, x, 128L * HW,
                             g_t, 384L * HW, pb);
}
__global__ __launch_bounds__(128) void k4_gemm(float* __restrict__ out) {
    mmasync_body<256, true>(g_Ah, g_Al, 128L * 256, g_yh, g_yl, nullptr, 256L * HW,
                            out, 128L * HW, nullptr);
}

// ---------------- dual grouped conv (3x3 + 5x5 sharing input pair) ----------------
// Retiled: 32x64 output per CTA, 128 threads, ~20.7KB smem -> 6 CTAs/SM so
// the exposed halo-load latency of one CTA is covered by five others' compute.
// Halo tile: 36 rows x 72 cols per channel (float4-aligned, division-free load).
#define CONV_ROW 72
#define CONV_CH (36 * CONV_ROW)

template <int MODE>
__global__ __launch_bounds__(128, 6) void dualconv_k(
    const float* __restrict__ in_ext,
    const float* __restrict__ w3, const float* __restrict__ b3,
    const float* __restrict__ w5, const float* __restrict__ b5)
{
    const int Cin = (MODE == 0) ? 384 : 128;
    const float* in = (MODE == 0) ? (const float*)g_t : in_ext;

    __shared__ float s[2 * CONV_CH];
    __shared__ float sw[68];

    const int tile = blockIdx.x;                 // 0..7: 4 row-tiles x 2 col-tiles
    const int oy0 = (tile >> 1) * 32;
    const int ox0 = (tile & 1) * 64;
    const int g = blockIdx.y;
    const long bz = blockIdx.z;
    const int tid = threadIdx.x;
    const int ttx = tid & 15, tty = tid >> 4;    // 16x8 threads, 4x4 px each
    const int py0 = tty * 4, px0 = ttx * 4;

    const float* in0 = in + (bz * Cin + 2 * g) * (long)HW;

    // ---- vectorized halo load: rows 0..35 (gy = oy0-2+row), cols 0..71 (gx = ox0-4+col)
    {
        const int lr = tid >> 4;     // 0..7: row within pass
        const int lc = tid & 15;     // chunk 0..15 (plus 16/17 for lc<2)
#pragma unroll
        for (int ch = 0; ch < 2; ch++) {
            const float* inc = in0 + ch * HW;
            float* sch = s + ch * CONV_CH;
#pragma unroll
            for (int rp = 0; rp < 40; rp += 8) {
                int r = rp + lr;
                if (r < 36) {
                    int gy = oy0 - 2 + r;
                    bool rowok = (unsigned)gy < 128u;
                    const float* rowp = inc + gy * IMG;
                    {
                        int gx0 = ox0 - 4 + lc * 4;
                        float4 v = make_float4(0.f, 0.f, 0.f, 0.f);
                        if (rowok && (unsigned)gx0 < 125u) v = *(const float4*)(rowp + gx0);
                        *(float4*)(sch + r * CONV_ROW + lc * 4) = v;
                    }
                    if (lc < 2) {
                        int j = 16 + lc;
                        int gx0 = ox0 - 4 + j * 4;
                        float4 v = make_float4(0.f, 0.f, 0.f, 0.f);
                        if (rowok && (unsigned)gx0 < 125u) v = *(const float4*)(rowp + gx0);
                        *(float4*)(sch + r * CONV_ROW + j * 4) = v;
                    }
                }
            }
        }
    }
    if (tid < 50) sw[tid] = w5[g * 50 + tid];
    else if (tid < 68) sw[tid] = w3[g * 18 + (tid - 50)];
    __syncthreads();

    const float bias3 = b3[g], bias5 = b5[g];
    float* f3 = nullptr; long y3 = -1;
    float* f5 = nullptr; long y5 = -1;
    if (MODE == 0) {
        if (g < 128) f3 = &g_q[(bz * 128 + g) * HW];
        else         f3 = &g_k[(bz * 128 + (g - 128)) * HW];
        if (g < 64)  f5 = &g_k[(bz * 128 + 64 + g) * HW];
        else         y5 = (bz * 256 + (g - 64)) * HW;
    } else {
        y3 = (bz * 256 + 128 + g) * HW;
        y5 = (bz * 256 + 192 + g) * HW;
    }

#pragma unroll
    for (int half = 0; half < 2; half++) {
        float a3[2][4], a5[2][4];
#pragma unroll
        for (int i = 0; i < 2; i++)
#pragma unroll
            for (int j = 0; j < 4; j++) { a3[i][j] = 0.f; a5[i][j] = 0.f; }

#pragma unroll
        for (int ic = 0; ic < 2; ++ic) {
            const float* sc = s + ic * CONV_CH + (py0 + half * 2) * CONV_ROW + px0 + 2;
            float r[6][8];
#pragma unroll
            for (int dy = 0; dy < 6; dy++)
#pragma unroll
                for (int dx = 0; dx < 8; dx++) r[dy][dx] = sc[dy * CONV_ROW + dx];
            const float* w5s = sw + ic * 25;
#pragma unroll
            for (int t = 0; t < 25; t++) {
                float wv = w5s[t];
                int ky = t / 5, kx = t % 5;
#pragma unroll
                for (int oy = 0; oy < 2; oy++)
#pragma unroll
                    for (int ox = 0; ox < 4; ox++)
                        a5[oy][ox] += r[oy + ky][ox + kx] * wv;
            }
            const float* w3s = sw + 50 + ic * 9;
#pragma unroll
            for (int t = 0; t < 9; t++) {
                float wv = w3s[t];
                int ky = t / 3, kx = t % 3;
#pragma unroll
                for (int oy = 0; oy < 2; oy++)
#pragma unroll
                    for (int ox = 0; ox < 4; ox++)
                        a3[oy][ox] += r[oy + 1 + ky][ox + 1 + kx] * wv;
            }
        }

#pragma unroll
        for (int oy = 0; oy < 2; oy++) {
            int off = (oy0 + py0 + half * 2 + oy) * IMG + ox0 + px0;
#pragma unroll
            for (int ox = 0; ox < 4; ox++) {
                float v3 = a3[oy][ox] + bias3;
                float v5 = a5[oy][ox] + bias5;
                if (f3) f3[off + ox] = v3;
                else { __nv_bfloat16 h, l; split2(v3, h, l); g_yh[y3 + off + ox] = h; g_yl[y3 + off + ox] = l; }
                if (f5) f5[off + ox] = v5;
                else { __nv_bfloat16 h, l; split2(v5, h, l); g_yh[y5 + off + ox] = h; g_yl[y5 + off + ox] = l; }
            }
        }
    }
}

// ---------------- gram: per (b,h): G[16][16] = q @ k^T over pixels + sq norms ------
__global__ __launch_bounds__(256) void gram_k()
{
    const int bh = blockIdx.x;
    const int slice = blockIdx.y;
    const int b = bh >> 3, h = bh & 7;
    const float* qp = g_q + (long)(b * 128 + h * 16) * HW + slice * 1024;
    const float* kp = g_k + (long)(b * 128 + h * 16) * HW + slice * 1024;

    __shared__ float sq[64][17];
    __shared__ float sk[64][17];
    const int tid = threadIdx.x;
    const int phase = tid & 15, dg = (tid >> 4) & 3, eg = tid >> 6;

    float acc[4][4], aq[4], ak[4];
#pragma unroll
    for (int i = 0; i < 4; i++) {
        aq[i] = 0.f; ak[i] = 0.f;
#pragma unroll
        for (int j = 0; j < 4; j++) acc[i][j] = 0.f;
    }

    for (int blk = 0; blk < 16; ++blk) {
        for (int idx = tid; idx < 1024; idx += 256) {
            int d = idx >> 6, p = idx & 63;
            sq[p][d] = qp[(long)d * HW + blk * 64 + p];
            sk[p][d] = kp[(long)d * HW + blk * 64 + p];
        }
        __syncthreads();
        for (int p = phase; p < 64; p += 16) {
            float qv[4], kv[4];
#pragma unroll
            for (int i = 0; i < 4; i++) qv[i] = sq[p][dg * 4 + i];
#pragma unroll
            for (int j = 0; j < 4; j++) kv[j] = sk[p][eg * 4 + j];
#pragma unroll
            for (int i = 0; i < 4; i++)
#pragma unroll
                for (int j = 0; j < 4; j++) acc[i][j] += qv[i] * kv[j];
            if (eg == 0) {
#pragma unroll
                for (int i = 0; i < 4; i++) aq[i] += qv[i] * qv[i];
            }
            if (dg == 0) {
#pragma unroll
                for (int j = 0; j < 4; j++) ak[j] += kv[j] * kv[j];
            }
        }
        __syncthreads();
    }

    __shared__ float sG[288];
    for (int idx = tid; idx < 288; idx += 256) sG[idx] = 0.f;
    __syncthreads();
#pragma unroll
    for (int i = 0; i < 4; i++)
#pragma unroll
        for (int j = 0; j < 4; j++)
            atomicAdd(&sG[(dg * 4 + i) * 16 + eg * 4 + j], acc[i][j]);
    if (eg == 0) {
#pragma unroll
        for (int i = 0; i < 4; i++) atomicAdd(&sG[256 + dg * 4 + i], aq[i]);
    }
    if (dg == 0) {
#pragma unroll
        for (int j = 0; j < 4; j++) atomicAdd(&sG[272 + eg * 4 + j], ak[j]);
    }
    __syncthreads();
    float* gg = g_gram + bh * 288;
    for (int idx = tid; idx < 288; idx += 256) atomicAdd(gg + idx, sG[idx]);
}

// ---------------- attn: normalize gram, softmax, fold with proj into A (bf16 split) --
__global__ __launch_bounds__(256) void attn_k(
    const float* __restrict__ temp, const float* __restrict__ proj_w)
{
    const int b = blockIdx.x;
    const int part = blockIdx.y;
    const int tid = threadIdx.x;
    const long aBase = (long)b * 128 * 256;

    if (part == 8) {
        for (int idx = tid; idx < 128 * 128; idx += 256) {
            int c = idx >> 7, j = idx & 127;
            __nv_bfloat16 h, l;
            split2(proj_w[c * 256 + 128 + j], h, l);
            g_Ah[aBase + c * 256 + 128 + j] = h;
            g_Al[aBase + c * 256 + 128 + j] = l;
        }
        return;
    }
    const int h = part;
    const float* gg = g_gram + (b * 8 + h) * 288;
    __shared__ float sA[256], sqn[16], skn[16], srm[16], srs[16];
    if (tid < 16) {
        sqn[tid] = fmaxf(sqrtf(gg[256 + tid]), 1e-12f);
        skn[tid] = fmaxf(sqrtf(gg[272 + tid]), 1e-12f);
    }
    __syncthreads();
    const int d = tid >> 4, e = tid & 15;
    float val = gg[d * 16 + e] / (sqn[d] * skn[e]) * temp[h];
    sA[tid] = val;
    __syncthreads();
    if (e == 0) {
        float m = -1e30f;
        for (int j = 0; j < 16; j++) m = fmaxf(m, sA[d * 16 + j]);
        srm[d] = m;
    }
    __syncthreads();
    float p = expf(val - srm[d]);
    sA[tid] = p;
    __syncthreads();
    if (e == 0) {
        float ssum = 0.f;
        for (int j = 0; j < 16; j++) ssum += sA[d * 16 + j];
        srs[d] = ssum;
    }
    __syncthreads();
    sA[tid] = p / srs[d];
    __syncthreads();
    for (int o = tid; o < 2048; o += 256) {
        int c = o >> 4, ee = o & 15;
        float accv = 0.f;
#pragma unroll
        for (int dd = 0; dd < 16; dd++)
            accv += proj_w[c * 256 + h * 16 + dd] * sA[dd * 16 + ee];
        __nv_bfloat16 hh, ll;
        split2(accv, hh, ll);
        g_Ah[aBase + c * 256 + h * 16 + ee] = hh;
        g_Al[aBase + c * 256 + h * 16 + ee] = ll;
    }
}

// ---------------- launch ----------------
extern "C" void kernel_launch(void* const* d_in, const int* in_sizes, int n_in,
                              void* d_out, int out_size)
{
    const float* x      = (const float*)d_in[0];
    const float* pos_w  = (const float*)d_in[1];
    const float* pos_b  = (const float*)d_in[2];
    const float* qd3_w  = (const float*)d_in[3];
    const float* qd3_b  = (const float*)d_in[4];
    const float* qd5_w  = (const float*)d_in[5];
    const float* qd5_b  = (const float*)d_in[6];
    const float* temp   = (const float*)d_in[7];
    const float* d3_w   = (const float*)d_in[8];
    const float* d3_b   = (const float*)d_in[9];
    const float* d5_w   = (const float*)d_in[10];
    const float* d5_b   = (const float*)d_in[11];
    const float* proj_w = (const float*)d_in[12];
    float* out = (float*)d_out;

    zero_gram_k<<<72, 256>>>();
    convert_w_k<<<48, 256>>>(pos_w);
    k1_gemm<<<dim3(128, 6, 8), 128>>>(x, pos_b);
    dualconv_k<0><<<dim3(8, 192, 8), 128>>>(nullptr, qd3_w, qd3_b, qd5_w, qd5_b);
    dualconv_k<1><<<dim3(8, 64, 8), 128>>>(x, d3_w, d3_b, d5_w, d5_b);
    gram_k<<<dim3(64, 16), 256>>>();
    attn_k<<<dim3(8, 9), 256>>>(temp, proj_w);
    k4_gemm<<<dim3(128, 2, 8), 128>>>(out);
}